// round 4
// baseline (speedup 1.0000x reference)
#include <cuda_runtime.h>
#include <cstddef>

// ---------------------------------------------------------------------------
// Seq2Seq LSTM, round 2: packed fp32x2 FFMA + transposed hidden state +
// double-buffered weight staging.
//
// Each CTA owns S_TILE=32 batch samples, runs all 110 recurrence steps.
// 256 threads = 2 sample-groups x 128 gate lanes. Lane j computes gate rows
// {j, j+128, j+256, j+384}; samples are processed in PAIRS packed into
// 64-bit registers driven by fma.rn.f32x2 (2 fp32 MACs per issue slot).
//
// Hidden state is stored transposed in SMEM: hT[hidden][sample] with a
// 36-float row stride (rows 16B-aligned, sample pairs contiguous ->
// broadcast LDS.128 on the read side, 4-way-conflict STS.128 on the rare
// write side).
//
// The 512x128 weight matrices are streamed from L2 each step through a
// double-buffered SMEM tile: LDG of tile k+1 (registers) overlaps compute
// of tile k; one __syncthreads per tile.
// ---------------------------------------------------------------------------

#define THREADS 256
#define SG      16              // samples per group (8 pairs)
#define S_TILE  32              // samples per CTA
#define KT      16              // K tile for weight staging
#define WSTR    (KT + 1)        // padded stride, conflict-free scalar LDS
#define HSTR    36              // transposed-h row stride (16B aligned rows)

constexpr int H      = 128;
constexpr int G4     = 512;
constexpr int INF    = 6;
constexpr int OUTF   = 2;
constexpr int T_HIST = 50;
constexpr int T_OUT  = 60;
constexpr int A_     = 8;
constexpr int B_     = 16384;

typedef unsigned long long ull;

struct Smem {
  float w2[2 * G4 * WSTR];   // double-buffered weight tile (69632 B)
  float hT0[H * HSTR];       // layer-0 hidden, transposed  (18432 B)
  float hT1[H * HSTR];       // layer-1 hidden, transposed  (18432 B)
  float xT[8 * S_TILE];      // input, transposed [feat][sample] (1024 B)
  float wih0e[G4 * 8];       // enc_Wih0 512x6 padded       (16384 B)
  float wih0d[G4 * 4];       // dec_Wih0 512x2 padded       (8192 B)
  float outW[2 * H];
  float b[4 * G4];           // eb0 | eb1 | db0 | db1
  float outb[4];
  float st[4];
};

// ---- fp32x2 helpers -------------------------------------------------------
__device__ __forceinline__ ull pack2(float v) {
  ull r; unsigned u = __float_as_uint(v);
  asm("mov.b64 %0, {%1, %1};" : "=l"(r) : "r"(u));
  return r;
}
__device__ __forceinline__ void unpack2(ull v, float& lo, float& hi) {
  unsigned a, b;
  asm("mov.b64 {%0, %1}, %2;" : "=r"(a), "=r"(b) : "l"(v));
  lo = __uint_as_float(a); hi = __uint_as_float(b);
}
__device__ __forceinline__ void ffma2(ull& d, ull a, ull b) {
  asm("fma.rn.f32x2 %0, %1, %2, %0;" : "+l"(d) : "l"(a), "l"(b));
}

__device__ __forceinline__ float sigmoidf_(float v) {
  return 1.0f / (1.0f + __expf(-v));
}
__device__ __forceinline__ float tanhf_(float v) {
  float ax = fabsf(v);
  float e  = __expf(-2.0f * ax);
  float r  = __fdividef(1.0f - e, 1.0f + e);
  return copysignf(r, v);
}

__device__ __forceinline__ void init_acc(ull (&acc)[4][8], const float* bptr, int j) {
#pragma unroll
  for (int g = 0; g < 4; ++g) {
    ull bv = pack2(bptr[g * H + j]);
#pragma unroll
    for (int p = 0; p < 8; ++p) acc[g][p] = bv;
  }
}

// ---- weight staging (register double buffer across KT tiles) --------------
__device__ __forceinline__ void stage_ldg(float4 (&r)[8], const float* __restrict__ Wg,
                                          int k0, int tid) {
#pragma unroll
  for (int u = 0; u < 8; ++u) {
    int idx = tid + u * THREADS;          // 0..2047 covers 512 rows x 16 cols
    int row = idx >> 2;
    int c4  = (idx & 3) << 2;
    r[u] = *reinterpret_cast<const float4*>(Wg + row * H + k0 + c4);
  }
}
__device__ __forceinline__ void stage_sts(const float4 (&r)[8], float* wb, int tid) {
#pragma unroll
  for (int u = 0; u < 8; ++u) {
    int idx = tid + u * THREADS;
    int row = idx >> 2;
    int c4  = (idx & 3) << 2;
    float* d = wb + row * WSTR + c4;
    d[0] = r[u].x; d[1] = r[u].y; d[2] = r[u].z; d[3] = r[u].w;
  }
}

// acc += W @ srcT for this thread's 4 gate rows and 8 sample pairs.
__device__ __forceinline__ void accum128(ull (&acc)[4][8],
                                         const float* __restrict__ Wg,
                                         const float* __restrict__ srcT,
                                         float* __restrict__ wbuf,
                                         int j, int s0, int tid) {
  float4 r[8];
  stage_ldg(r, Wg, 0, tid);
  __syncthreads();                      // prior readers of wbuf are done
  int cur = 0;
#pragma unroll 1
  for (int t8 = 0; t8 < 8; ++t8) {
    stage_sts(r, wbuf + cur * (G4 * WSTR), tid);
    __syncthreads();
    if (t8 < 7) stage_ldg(r, Wg, (t8 + 1) * KT, tid);   // overlap next tile
    const float* wb = wbuf + cur * (G4 * WSTR);
    const int k0 = t8 * KT;
#pragma unroll
    for (int c = 0; c < KT; ++c) {
      const float* hrow = srcT + (k0 + c) * HSTR + s0;
      ulonglong2 a0 = *reinterpret_cast<const ulonglong2*>(hrow);
      ulonglong2 a1 = *reinterpret_cast<const ulonglong2*>(hrow + 4);
      ulonglong2 a2 = *reinterpret_cast<const ulonglong2*>(hrow + 8);
      ulonglong2 a3 = *reinterpret_cast<const ulonglong2*>(hrow + 12);
      ull hp0 = a0.x, hp1 = a0.y, hp2 = a1.x, hp3 = a1.y;
      ull hp4 = a2.x, hp5 = a2.y, hp6 = a3.x, hp7 = a3.y;
#pragma unroll
      for (int g = 0; g < 4; ++g) {
        ull w = pack2(wb[(j + (g << 7)) * WSTR + c]);
        ffma2(acc[g][0], w, hp0); ffma2(acc[g][1], w, hp1);
        ffma2(acc[g][2], w, hp2); ffma2(acc[g][3], w, hp3);
        ffma2(acc[g][4], w, hp4); ffma2(acc[g][5], w, hp5);
        ffma2(acc[g][6], w, hp6); ffma2(acc[g][7], w, hp7);
      }
    }
    cur ^= 1;
  }
}

// small input contribution (nf features) from transposed xT using packed pairs
__device__ __forceinline__ void accum_small(ull (&acc)[4][8],
                                            const float* __restrict__ wsm, int wstr,
                                            const float* __restrict__ xT, int nf,
                                            int j, int s0) {
  for (int i = 0; i < nf; ++i) {
    const float* xrow = xT + i * S_TILE + s0;
    ulonglong2 a0 = *reinterpret_cast<const ulonglong2*>(xrow);
    ulonglong2 a1 = *reinterpret_cast<const ulonglong2*>(xrow + 4);
    ulonglong2 a2 = *reinterpret_cast<const ulonglong2*>(xrow + 8);
    ulonglong2 a3 = *reinterpret_cast<const ulonglong2*>(xrow + 12);
    ull hp[8] = {a0.x, a0.y, a1.x, a1.y, a2.x, a2.y, a3.x, a3.y};
#pragma unroll
    for (int g = 0; g < 4; ++g) {
      ull w = pack2(wsm[(j + (g << 7)) * wstr + i]);
#pragma unroll
      for (int p = 0; p < 8; ++p) ffma2(acc[g][p], w, hp[p]);
    }
  }
}

__device__ __forceinline__ void cell_update(ull (&acc)[4][8], float* cr, float* hnew) {
#pragma unroll
  for (int p = 0; p < 8; ++p) {
    float i0, i1, f0, f1, g0, g1, o0, o1;
    unpack2(acc[0][p], i0, i1);
    unpack2(acc[1][p], f0, f1);
    unpack2(acc[2][p], g0, g1);
    unpack2(acc[3][p], o0, o1);
    float c0 = sigmoidf_(f0) * cr[2 * p]     + sigmoidf_(i0) * tanhf_(g0);
    float c1 = sigmoidf_(f1) * cr[2 * p + 1] + sigmoidf_(i1) * tanhf_(g1);
    cr[2 * p]     = c0;
    cr[2 * p + 1] = c1;
    hnew[2 * p]     = sigmoidf_(o0) * tanhf_(c0);
    hnew[2 * p + 1] = sigmoidf_(o1) * tanhf_(c1);
  }
}

__device__ __forceinline__ void write_h(float* hT, const float* hnew, int j, int s0) {
  float* base = hT + j * HSTR + s0;
#pragma unroll
  for (int m = 0; m < 4; ++m) {
    *reinterpret_cast<float4*>(base + 4 * m) =
        make_float4(hnew[4 * m], hnew[4 * m + 1], hnew[4 * m + 2], hnew[4 * m + 3]);
  }
}

__global__ void __launch_bounds__(THREADS)
lstm_seq2seq_kernel(const float* __restrict__ history,
                    const float* __restrict__ start_token,
                    const float* __restrict__ eWih0, const float* __restrict__ eWhh0,
                    const float* __restrict__ eb0,
                    const float* __restrict__ eWih1, const float* __restrict__ eWhh1,
                    const float* __restrict__ eb1,
                    const float* __restrict__ dWih0, const float* __restrict__ dWhh0,
                    const float* __restrict__ db0,
                    const float* __restrict__ dWih1, const float* __restrict__ dWhh1,
                    const float* __restrict__ db1,
                    const float* __restrict__ outW, const float* __restrict__ outb,
                    float* __restrict__ out) {
  extern __shared__ float smraw[];
  Smem& s = *reinterpret_cast<Smem*>(smraw);

  const int tid = threadIdx.x;
  const int j   = tid & 127;
  const int s0  = (tid >> 7) * SG;
  const int b0  = blockIdx.x * S_TILE;

  // ---- one-time SMEM setup ----
  for (int idx = tid; idx < G4 * INF; idx += THREADS) {
    int r = idx / INF, c = idx % INF;
    s.wih0e[r * 8 + c] = eWih0[idx];
  }
  for (int idx = tid; idx < G4 * OUTF; idx += THREADS) {
    int r = idx >> 1, c = idx & 1;
    s.wih0d[r * 4 + c] = dWih0[idx];
  }
  for (int idx = tid; idx < 2 * H; idx += THREADS) s.outW[idx] = outW[idx];
  for (int idx = tid; idx < G4; idx += THREADS) {
    s.b[idx]          = eb0[idx];
    s.b[G4 + idx]     = eb1[idx];
    s.b[2 * G4 + idx] = db0[idx];
    s.b[3 * G4 + idx] = db1[idx];
  }
  if (tid < 2) { s.outb[tid] = outb[tid]; s.st[tid] = start_token[tid]; }
  for (int idx = tid; idx < H * HSTR; idx += THREADS) { s.hT0[idx] = 0.0f; s.hT1[idx] = 0.0f; }

  float c0r[SG], c1r[SG];
#pragma unroll
  for (int k = 0; k < SG; ++k) { c0r[k] = 0.0f; c1r[k] = 0.0f; }

  ull  acc[4][8];
  float hnew[SG];

  __syncthreads();

  // ================= ENCODER =================
  for (int t = 0; t < T_HIST; ++t) {
    if (tid < S_TILE * INF) {
      int ss = tid / INF, i = tid % INF;
      s.xT[i * S_TILE + ss] =
          history[(((size_t)(b0 + ss) * A_ + 0) * T_HIST + t) * INF + i];
    }
    __syncthreads();

    // layer 0
    init_acc(acc, &s.b[0], j);
    accum_small(acc, s.wih0e, 8, s.xT, INF, j, s0);
    accum128(acc, eWhh0, s.hT0, s.w2, j, s0, tid);
    cell_update(acc, c0r, hnew);
    __syncthreads();                 // readers of old hT0 done
    write_h(s.hT0, hnew, j, s0);
    __syncthreads();

    // layer 1
    init_acc(acc, &s.b[G4], j);
    accum128(acc, eWih1, s.hT0, s.w2, j, s0, tid);
    accum128(acc, eWhh1, s.hT1, s.w2, j, s0, tid);
    cell_update(acc, c1r, hnew);
    __syncthreads();
    write_h(s.hT1, hnew, j, s0);
    __syncthreads();
  }

  // decoder start token
  if (tid < S_TILE * OUTF) {
    int ss = tid >> 1, o = tid & 1;
    s.xT[o * S_TILE + ss] = s.st[o];
  }
  __syncthreads();

  // ================= DECODER =================
  for (int t = 0; t < T_OUT; ++t) {
    // layer 0
    init_acc(acc, &s.b[2 * G4], j);
    accum_small(acc, s.wih0d, 4, s.xT, OUTF, j, s0);
    accum128(acc, dWhh0, s.hT0, s.w2, j, s0, tid);
    cell_update(acc, c0r, hnew);
    __syncthreads();
    write_h(s.hT0, hnew, j, s0);
    __syncthreads();

    // layer 1
    init_acc(acc, &s.b[3 * G4], j);
    accum128(acc, dWih1, s.hT0, s.w2, j, s0, tid);
    accum128(acc, dWhh1, s.hT1, s.w2, j, s0, tid);
    cell_update(acc, c1r, hnew);
    __syncthreads();
    write_h(s.hT1, hnew, j, s0);
    __syncthreads();

    // projection + feedback
    if (tid < S_TILE * OUTF) {
      int ss = tid >> 1, o = tid & 1;
      float a = s.outb[o];
      const float* wrow = &s.outW[o * H];
#pragma unroll 16
      for (int k = 0; k < H; ++k) a = fmaf(wrow[k], s.hT1[k * HSTR + ss], a);
      out[((size_t)(b0 + ss) * T_OUT + t) * OUTF + o] = a;
      s.xT[o * S_TILE + ss] = a;
    }
    __syncthreads();
  }
}

extern "C" void kernel_launch(void* const* d_in, const int* in_sizes, int n_in,
                              void* d_out, int out_size) {
  const float* history     = (const float*)d_in[0];
  const float* start_token = (const float*)d_in[1];
  const float* eWih0       = (const float*)d_in[2];
  const float* eWhh0       = (const float*)d_in[3];
  const float* eb0         = (const float*)d_in[4];
  const float* eWih1       = (const float*)d_in[5];
  const float* eWhh1       = (const float*)d_in[6];
  const float* eb1         = (const float*)d_in[7];
  const float* dWih0       = (const float*)d_in[8];
  const float* dWhh0       = (const float*)d_in[9];
  const float* db0         = (const float*)d_in[10];
  const float* dWih1       = (const float*)d_in[11];
  const float* dWhh1       = (const float*)d_in[12];
  const float* db1         = (const float*)d_in[13];
  const float* outW        = (const float*)d_in[14];
  const float* outb        = (const float*)d_in[15];
  float* out               = (float*)d_out;

  (void)in_sizes; (void)n_in; (void)out_size;

  cudaFuncSetAttribute(lstm_seq2seq_kernel,
                       cudaFuncAttributeMaxDynamicSharedMemorySize,
                       (int)sizeof(Smem));

  dim3 grid(B_ / S_TILE);   // 512 CTAs
  lstm_seq2seq_kernel<<<grid, THREADS, sizeof(Smem)>>>(
      history, start_token,
      eWih0, eWhh0, eb0, eWih1, eWhh1, eb1,
      dWih0, dWhh0, db0, dWih1, dWhh1, db1,
      outW, outb, out);
}

// round 7
// speedup vs baseline: 1.7780x; 1.7780x over previous
#include <cuda_runtime.h>
#include <cuda_fp16.h>
#include <cstdint>
#include <cstddef>

typedef unsigned int u32; typedef unsigned short u16;

// ---- smem layout (bytes) ----
#define H0HI 0u
#define H0LO 19456u
#define H1HI 38912u
#define H1LO 58368u
#define BBUF 77824u      // 2 x 9216 B-staging
#define BIAS 96256u      // 4*512 f32 (gate-interleaved)
#define OUTW 104448u     // 256 f32
#define PSUM 105472u     // 64*2 f32
#define SMSZ 105984u

// prepped weight stream: 200 units x 9216B (hi chunk 4608B | lo chunk 4608B)
// unit u in phase: u<36: L0 p=u/9,kb=u%9 (kb8=x);  u>=36: v=u-36,p=v/16,kq=v%16
__device__ u16 g_B[200 * 4608];

__device__ __forceinline__ u32 smem_u32(const void* p){
  u32 a; asm("{ .reg .u64 t; cvta.to.shared.u64 t, %1; cvt.u32.u64 %0, t; }":"=r"(a):"l"(p)); return a;
}
__device__ __forceinline__ float sigm(float v){ return 1.0f/(1.0f+__expf(-v)); }
__device__ __forceinline__ float tanh_(float v){
  float ax=fabsf(v), e=__expf(-2.0f*ax);
  return copysignf(__fdividef(1.0f-e,1.0f+e), v);
}
#define MMA(d,a0,a1,a2,a3,b0,b1) \
  asm volatile("mma.sync.aligned.m16n8k16.row.col.f32.f16.f16.f32 " \
    "{%0,%1,%2,%3},{%4,%5,%6,%7},{%8,%9},{%0,%1,%2,%3};" \
    :"+f"(d[0]),"+f"(d[1]),"+f"(d[2]),"+f"(d[3]) \
    :"r"(a0),"r"(a1),"r"(a2),"r"(a3),"r"(b0),"r"(b1))

// ===== prep: split weights to fp16 hi/lo, gate-interleaved, consumption order =====
__global__ void prep_kernel(const float* eWih0,const float* eWhh0,const float* eWih1,const float* eWhh1,
                            const float* dWih0,const float* dWhh0,const float* dWih1,const float* dWhh1){
  int blk=blockIdx.x, gu=blk>>1, split=blk&1, ph=gu/100, u=gu%100;
  const float* Wx = ph? dWih0 : eWih0;
  const float* M; int nf = ph?2:6, kb=0, isx=0, p;
  if(u<36){ p=u/9; int q=u%9; M = ph? dWhh0:eWhh0; if(q==8) isx=1; else kb=q; }
  else { int v=u-36; p=v/16; int kq=v%16;
         if(kq<8){ M=ph?dWih1:eWih1; kb=kq; } else { M=ph?dWhh1:eWhh1; kb=kq-8; } }
  u16* dst = g_B + (size_t)gu*4608 + split*2304;
  for(int e=threadIdx.x; e<2304; e+=128){
    int n=e/18, kp=e%18; float w=0.f;
    if(kp<16){
      int ng=p*128+n, j=ng>>2, gt=ng&3, wr=gt*128+j;
      if(isx){ if(kp<nf) w = Wx[wr*nf+kp]; }
      else w = M[wr*128 + kb*16 + kp];
    }
    __half hv = __float2half_rn(w);
    u16 ov;
    if(split==0) ov = *(u16*)&hv;
    else { __half lv = __float2half_rn(w - __half2float(hv)); ov = *(u16*)&lv; }
    dst[e] = ov;
  }
}

// ===== stage one 9216B unit via cp.async =====
__device__ __forceinline__ void stage(u32 smb, int tid, int unit, int buf){
  const char* src = (const char*)g_B + (size_t)unit*9216;
  u32 dst = smb + BBUF + (u32)buf*9216u;
#pragma unroll
  for(int i=0;i<3;++i){
    int e = tid + i*256;
    if(e<576)
      asm volatile("cp.async.cg.shared.global [%0], [%1], 16;"
        ::"r"(dst+(u32)e*16u),"l"(src+(size_t)e*16):"memory");
  }
  asm volatile("cp.async.commit_group;":::"memory");
}

// ===== per-unit MMA work (warp) =====
__device__ __forceinline__ void unitmma(char* sm, u32 ahi, int akb, int buf,
                                        int wm, int wn, int lane, float (&acc)[8][4]){
  int g=lane>>2, tq=lane&3;
  u32 ao = ahi + (u32)(((wm*16+g)*152 + akb*16 + tq*2)*2);
  u32 a0=*(u32*)(sm+ao),        a1=*(u32*)(sm+ao+2432);
  u32 a2=*(u32*)(sm+ao+16),     a3=*(u32*)(sm+ao+2448);
  u32 l0=*(u32*)(sm+ao+19456),  l1=*(u32*)(sm+ao+21888);
  u32 l2=*(u32*)(sm+ao+19472),  l3=*(u32*)(sm+ao+21904);
  u32 bb = BBUF + (u32)buf*9216u;
#pragma unroll
  for(int nt=0;nt<8;++nt){
    u32 bo = bb + (u32)((wn*64+nt*8+g)*36 + tq*4);
    u32 bh0=*(u32*)(sm+bo),      bh1=*(u32*)(sm+bo+16);
    u32 bl0=*(u32*)(sm+bo+4608), bl1=*(u32*)(sm+bo+4624);
    MMA(acc[nt], a0,a1,a2,a3, bh0,bh1);
    MMA(acc[nt], l0,l1,l2,l3, bh0,bh1);
    MMA(acc[nt], a0,a1,a2,a3, bl0,bl1);
  }
}

// ===== epilogue for one pass (no syncs; regs only) =====
__device__ __forceinline__ void epi(char* sm, float (&acc)[8][4], float* cb, u32* hb,
                                    int set, int p, int wn, int lane, int s, bool proj){
  int tq=lane&3, odd=lane&1;
  const float* bs = (const float*)(sm+BIAS) + set*512 + p*128 + wn*64;
  const float* ow = (const float*)(sm+OUTW);
  float y0=0.f, y1=0.f;
#pragma unroll
  for(int nt=0;nt<8;++nt){
    float s0 = odd? acc[nt][0]:acc[nt][2];
    float s1 = odd? acc[nt][1]:acc[nt][3];
    float r0 = __shfl_xor_sync(0xffffffffu, s0, 1);
    float r1 = __shfl_xor_sync(0xffffffffu, s1, 1);
    float gi = odd? r0 : acc[nt][0];
    float gf = odd? r1 : acc[nt][1];
    float gg = odd? acc[nt][2] : r0;
    float go = odd? acc[nt][3] : r1;
    float4 bv = *(const float4*)(bs + nt*8 + (tq>>1)*4);
    gi+=bv.x; gf+=bv.y; gg+=bv.z; go+=bv.w;
    float c = sigm(gf)*cb[nt] + sigm(gi)*tanh_(gg);
    cb[nt]=c;
    float h = sigm(go)*tanh_(c);
    __half hh=__float2half_rn(h);
    __half hl=__float2half_rn(h-__half2float(hh));
    hb[nt] = (u32)(*(u16*)&hh) | ((u32)(*(u16*)&hl)<<16);
    if(proj){ int j = p*32 + wn*16 + nt*2 + (tq>>1); y0 += h*ow[j]; y1 += h*ow[128+j]; }
  }
  if(proj){ float* ps=(float*)(sm+PSUM); atomicAdd(ps+s*2,y0); atomicAdd(ps+s*2+1,y1); }
}

__global__ void __launch_bounds__(256,1)
lstm_hmma_kernel(const float* __restrict__ history, const float* __restrict__ start_token,
                 const float* __restrict__ eb0, const float* __restrict__ eb1,
                 const float* __restrict__ db0, const float* __restrict__ db1,
                 const float* __restrict__ outWg, const float* __restrict__ outb,
                 float* __restrict__ out){
  extern __shared__ char sm[];
  const u32 smb = smem_u32(sm);
  const int tid=threadIdx.x, lane=tid&31, wid=tid>>5;
  const int wm=wid>>1, wn=wid&1, tq=lane&3;
  const int s = wm*16 + (lane>>2) + (lane&1)*8;   // this thread's sample row
  const int b0 = blockIdx.x*64;

  // init smem
  for(int i=tid;i<19456;i+=256) ((u32*)sm)[i]=0u;            // tiles zero (77824B)
  for(int i=tid;i<2048;i+=256){
    int st_=i>>9, n=i&511, j=n>>2, gt=n&3;
    const float* bp = st_==0?eb0: st_==1?eb1: st_==2?db0: db1;
    ((float*)(sm+BIAS))[i] = bp[gt*128+j];
  }
  if(tid<256) ((float*)(sm+OUTW))[tid]=outWg[tid];
  if(tid<128) ((float*)(sm+PSUM))[tid]=0.f;
  __syncthreads();

  float c0[32], c1[32]; u32 hst[32];
#pragma unroll
  for(int i=0;i<32;++i){ c0[i]=0.f; c1[i]=0.f; }

  int par=0;
  stage(smb,tid,0,0);     // prologue: first unit of step0

  for(int t=0;t<110;++t){
    const int ph = (t>=50);
    const int base = ph?100:0;
    const int nb = (t+1<110)? ((t+1>=50)?100:0) : base;
    // ---- x into h0 tile cols 128.. ----
    if(!ph){
      if(tid<64){
        const float* hp = history + (((size_t)(b0+tid)*8)*50 + (size_t)t)*6;
#pragma unroll
        for(int f=0;f<6;++f){
          float v=hp[f];
          __half hh=__float2half_rn(v), hl=__float2half_rn(v-__half2float(hh));
          *(u16*)(sm + H0HI + ((u32)tid*152+128+f)*2) = *(u16*)&hh;
          *(u16*)(sm + H0LO + ((u32)tid*152+128+f)*2) = *(u16*)&hl;
        }
      }
    } else if(t==50){
      if(tid<64){
#pragma unroll
        for(int f=0;f<6;++f){
          float v = (f<2)? start_token[f] : 0.f;
          __half hh=__float2half_rn(v), hl=__float2half_rn(v-__half2float(hh));
          *(u16*)(sm + H0HI + ((u32)tid*152+128+f)*2) = *(u16*)&hh;
          *(u16*)(sm + H0LO + ((u32)tid*152+128+f)*2) = *(u16*)&hl;
        }
      }
    }
    int idx=0;
    // ================= layer 0 =================
#pragma unroll
    for(int p=0;p<4;++p){
      float acc[8][4];
#pragma unroll
      for(int a=0;a<8;++a){acc[a][0]=0;acc[a][1]=0;acc[a][2]=0;acc[a][3]=0;}
#pragma unroll 1
      for(int kb=0;kb<9;++kb){
        int nxt = (idx<99)? base+idx+1 : nb;
        stage(smb,tid,nxt,par^1);
        asm volatile("cp.async.wait_group 1;":::"memory");
        __syncthreads();
        unitmma(sm, H0HI, kb, par, wm,wn,lane, acc);
        par^=1; ++idx;
      }
      epi(sm, acc, c0+p*8, hst+p*8, ph*2+0, p, wn, lane, s, false);
    }
    __syncthreads();   // all reads of old h0 done
#pragma unroll
    for(int p=0;p<4;++p)
#pragma unroll
      for(int nt=0;nt<8;++nt){
        int j = p*32 + wn*16 + nt*2 + (tq>>1);
        u32 v = hst[p*8+nt];
        *(u16*)(sm + H0HI + ((u32)s*152+(u32)j)*2) = (u16)v;
        *(u16*)(sm + H0LO + ((u32)s*152+(u32)j)*2) = (u16)(v>>16);
      }
    // ================= layer 1 =================
#pragma unroll
    for(int p=0;p<4;++p){
      float acc[8][4];
#pragma unroll
      for(int a=0;a<8;++a){acc[a][0]=0;acc[a][1]=0;acc[a][2]=0;acc[a][3]=0;}
#pragma unroll 1
      for(int kq=0;kq<16;++kq){
        int nxt = (idx<99)? base+idx+1 : nb;
        stage(smb,tid,nxt,par^1);
        asm volatile("cp.async.wait_group 1;":::"memory");
        __syncthreads();
        unitmma(sm, (kq<8)?H0HI:H1HI, kq&7, par, wm,wn,lane, acc);
        par^=1; ++idx;
      }
      epi(sm, acc, c1+p*8, hst+p*8, ph*2+1, p, wn, lane, s, ph!=0);
    }
    __syncthreads();   // all reads of old h1 + psum atomics done
#pragma unroll
    for(int p=0;p<4;++p)
#pragma unroll
      for(int nt=0;nt<8;++nt){
        int j = p*32 + wn*16 + nt*2 + (tq>>1);
        u32 v = hst[p*8+nt];
        *(u16*)(sm + H1HI + ((u32)s*152+(u32)j)*2) = (u16)v;
        *(u16*)(sm + H1LO + ((u32)s*152+(u32)j)*2) = (u16)(v>>16);
      }
    if(ph){
      if(tid<128){
        int ss=tid>>1, o=tid&1;
        float y = ((float*)(sm+PSUM))[tid] + outb[o];
        out[((size_t)(b0+ss)*60 + (size_t)(t-50))*2 + o] = y;
        ((float*)(sm+PSUM))[tid]=0.f;
        __half hh=__float2half_rn(y), hl=__float2half_rn(y-__half2float(hh));
        *(u16*)(sm + H0HI + ((u32)ss*152+128+(u32)o)*2) = *(u16*)&hh;
        *(u16*)(sm + H0LO + ((u32)ss*152+128+(u32)o)*2) = *(u16*)&hl;
      }
      __syncthreads();
    }
  }
  asm volatile("cp.async.wait_group 0;":::"memory");
}

extern "C" void kernel_launch(void* const* d_in, const int* in_sizes, int n_in,
                              void* d_out, int out_size){
  const float* history     = (const float*)d_in[0];
  const float* start_token = (const float*)d_in[1];
  const float* eWih0=(const float*)d_in[2],  *eWhh0=(const float*)d_in[3],  *eb0=(const float*)d_in[4];
  const float* eWih1=(const float*)d_in[5],  *eWhh1=(const float*)d_in[6],  *eb1=(const float*)d_in[7];
  const float* dWih0=(const float*)d_in[8],  *dWhh0=(const float*)d_in[9],  *db0=(const float*)d_in[10];
  const float* dWih1=(const float*)d_in[11], *dWhh1=(const float*)d_in[12], *db1=(const float*)d_in[13];
  const float* outW=(const float*)d_in[14],  *outb=(const float*)d_in[15];
  float* out=(float*)d_out;
  (void)in_sizes; (void)n_in; (void)out_size;

  cudaFuncSetAttribute(lstm_hmma_kernel, cudaFuncAttributeMaxDynamicSharedMemorySize, SMSZ);

  prep_kernel<<<400, 128>>>(eWih0,eWhh0,eWih1,eWhh1,dWih0,dWhh0,dWih1,dWhh1);
  lstm_hmma_kernel<<<256, 256, SMSZ>>>(history,start_token,eb0,eb1,db0,db1,outW,outb,out);
}

// round 9
// speedup vs baseline: 2.2257x; 1.2518x over previous
#include <cuda_runtime.h>
#include <cuda_fp16.h>
#include <cstdint>
#include <cstddef>

typedef unsigned int u32; typedef unsigned short u16;

// ---- smem layout (bytes) ----
#define H0HI 0u
#define H0LO 19456u
#define H1HI 38912u
#define H1LO 58368u
#define BBUF 77824u      // 4 x 8192 B-staging ring
#define BIAS 110592u     // 4*512 f32 gate-interleaved
#define OUTW 118784u
#define PSUM 119808u
#define MBAR 120320u     // full[4] @ +0, empty[4] @ +32
#define SMSZ 120448u

// prepped weight stream: 200 units x 8192B, fragment-order:
// unit: [nt 0..15][lane 0..31][bh0,bh1,bl0,bl1] (16B per lane)
__device__ uint4 g_B[200 * 512];

__device__ __forceinline__ u32 smem_u32(const void* p){
  u32 a; asm("{ .reg .u64 t; cvta.to.shared.u64 t, %1; cvt.u32.u64 %0, t; }":"=r"(a):"l"(p)); return a;
}
__device__ __forceinline__ float sigm(float v){ return 1.0f/(1.0f+__expf(-v)); }
__device__ __forceinline__ float tanh_(float v){
  float ax=fabsf(v), e=__expf(-2.0f*ax);
  return copysignf(__fdividef(1.0f-e,1.0f+e), v);
}
#define MMA(d,a0,a1,a2,a3,b0,b1) \
  asm volatile("mma.sync.aligned.m16n8k16.row.col.f32.f16.f16.f32 " \
    "{%0,%1,%2,%3},{%4,%5,%6,%7},{%8,%9},{%0,%1,%2,%3};" \
    :"+f"(d[0]),"+f"(d[1]),"+f"(d[2]),"+f"(d[3]) \
    :"r"(a0),"r"(a1),"r"(a2),"r"(a3),"r"(b0),"r"(b1))

__device__ __forceinline__ void mbar_init(u32 mb,u32 c){
  asm volatile("mbarrier.init.shared.b64 [%0], %1;"::"r"(mb),"r"(c):"memory");
}
__device__ __forceinline__ void mbar_wait(u32 mb,u32 ph){
  u32 done;
  asm volatile("{\n\t.reg .pred p;\n\t"
    "mbarrier.try_wait.parity.acquire.cta.shared::cta.b64 p, [%1], %2;\n\t"
    "selp.b32 %0, 1, 0, p;\n\t}":"=r"(done):"r"(mb),"r"(ph):"memory");
  if(!done){
    asm volatile("{\n\t.reg .pred P1;\n\tWL_%=:\n\t"
      "mbarrier.try_wait.parity.acquire.cta.shared::cta.b64 P1, [%0], %1, 0x989680;\n\t"
      "@P1 bra.uni WD_%=;\n\tbra.uni WL_%=;\n\tWD_%=:\n\t}"::"r"(mb),"r"(ph):"memory");
  }
}
#define BARC() asm volatile("bar.sync 1, 256;":::"memory")   // consumer warps only

// ===== prep: fragment-order fp16 hi/lo weight stream =====
__global__ void prep_kernel(const float* eWih0,const float* eWhh0,const float* eWih1,const float* eWhh1,
                            const float* dWih0,const float* dWhh0,const float* dWih1,const float* dWhh1){
  int gu=blockIdx.x, ph=gu/100, u=gu%100;
  const float* Wx = ph? dWih0 : eWih0;
  const float* M=nullptr; int nf=ph?2:6, kb=0, isx=0, p;
  if(u<36){ p=u/9; int q9=u%9; M=ph?dWhh0:eWhh0; if(q9==8) isx=1; else kb=q9; }
  else { int v=u-36; p=v/16; int kq=v%16;
         if(kq<8){ M=ph?dWih1:eWih1; kb=kq; } else { M=ph?dWhh1:eWhh1; kb=kq-8; } }
  u32* dst = (u32*)g_B + (size_t)gu*2048;
  for(int e=threadIdx.x; e<2048; e+=256){
    int nt=e>>7, lane=(e>>2)&31, q=e&3;
    int g=lane>>2, tq=lane&3;
    int n_loc=nt*8+g, k_loc=tq*2+(q&1)*8, lo=(q>=2);
    int ng=p*128+n_loc, j=ng>>2, gt=ng&3, wr=gt*128+j;
    float w0=0.f, w1=0.f;
    if(isx){
      if(k_loc<nf)   w0=Wx[wr*nf+k_loc];
      if(k_loc+1<nf) w1=Wx[wr*nf+k_loc+1];
    } else {
      w0=M[wr*128+kb*16+k_loc]; w1=M[wr*128+kb*16+k_loc+1];
    }
    __half h0=__float2half_rn(w0), h1=__float2half_rn(w1);
    u16 o0,o1;
    if(!lo){ o0=*(u16*)&h0; o1=*(u16*)&h1; }
    else{ __half l0=__float2half_rn(w0-__half2float(h0)), l1=__float2half_rn(w1-__half2float(h1));
          o0=*(u16*)&l0; o1=*(u16*)&l1; }
    dst[e] = (u32)o0 | ((u32)o1<<16);
  }
}

// ===== consumer: one unit of MMA =====
__device__ __forceinline__ void unitmma(char* sm, u32 ahi, int akb, int buf,
                                        int wm,int wn,int lane, float (&acc)[8][4]){
  int g=lane>>2, tq=lane&3;
  u32 ao = ahi + (u32)(((wm*16+g)*152 + akb*16 + tq*2)*2);
  u32 a0=*(u32*)(sm+ao),       a1=*(u32*)(sm+ao+2432);
  u32 a2=*(u32*)(sm+ao+16),    a3=*(u32*)(sm+ao+2448);
  u32 l0=*(u32*)(sm+ao+19456), l1=*(u32*)(sm+ao+21888);
  u32 l2=*(u32*)(sm+ao+19472), l3=*(u32*)(sm+ao+21904);
  u32 bb = BBUF + (u32)buf*8192u + (u32)((wn*8)*32+lane)*16u;
#pragma unroll
  for(int nt=0;nt<8;++nt){
    uint4 bv = *(uint4*)(sm + bb + (u32)nt*512u);
    MMA(acc[nt], a0,a1,a2,a3, bv.x,bv.y);
    MMA(acc[nt], l0,l1,l2,l3, bv.x,bv.y);
    MMA(acc[nt], a0,a1,a2,a3, bv.z,bv.w);
  }
}
__device__ __forceinline__ void consume(char* sm,u32 smb,int& i,int wm,int wn,int lane,
                                        u32 ahi,int akb,float (&acc)[8][4]){
  int b=i&3, r=i>>2; ++i;
  mbar_wait(smb+MBAR+(u32)b*8u, (u32)(r&1));
  unitmma(sm, ahi, akb, b, wm,wn,lane, acc);
  __syncwarp();
  if(lane==0)
    asm volatile("mbarrier.arrive.shared.b64 _, [%0];"::"r"(smb+MBAR+32u+(u32)b*8u):"memory");
}

// ===== epilogue for one 128-n pass =====
__device__ __forceinline__ void epi(char* sm, float (&acc)[8][4], float* cb, u32* hb,
                                    int set, int p, int wn, int lane, int s, bool proj){
  int tq=lane&3, odd=lane&1;
  const float* bs = (const float*)(sm+BIAS) + set*512 + p*128 + wn*64;
  const float* ow = (const float*)(sm+OUTW);
  float y0=0.f, y1=0.f;
#pragma unroll
  for(int nt=0;nt<8;++nt){
    float s0 = odd? acc[nt][0]:acc[nt][2];
    float s1 = odd? acc[nt][1]:acc[nt][3];
    float r0 = __shfl_xor_sync(0xffffffffu, s0, 1);
    float r1 = __shfl_xor_sync(0xffffffffu, s1, 1);
    float gi = odd? r0 : acc[nt][0];
    float gf = odd? r1 : acc[nt][1];
    float gg = odd? acc[nt][2] : r0;
    float go = odd? acc[nt][3] : r1;
    float4 bv = *(const float4*)(bs + nt*8 + (tq>>1)*4);
    gi+=bv.x; gf+=bv.y; gg+=bv.z; go+=bv.w;
    float c = sigm(gf)*cb[nt] + sigm(gi)*tanh_(gg);
    cb[nt]=c;
    float h = sigm(go)*tanh_(c);
    __half hh=__float2half_rn(h);
    __half hl=__float2half_rn(h-__half2float(hh));
    hb[nt] = (u32)(*(u16*)&hh) | ((u32)(*(u16*)&hl)<<16);
    if(proj){ int j = p*32 + wn*16 + nt*2 + (tq>>1); y0 += h*ow[j]; y1 += h*ow[128+j]; }
  }
  if(proj){ float* ps=(float*)(sm+PSUM); atomicAdd(ps+s*2,y0); atomicAdd(ps+s*2+1,y1); }
}

__global__ void __launch_bounds__(288,1)
lstm_hmma_kernel(const float* __restrict__ history, const float* __restrict__ start_token,
                 const float* __restrict__ eb0, const float* __restrict__ eb1,
                 const float* __restrict__ db0, const float* __restrict__ db1,
                 const float* __restrict__ outWg, const float* __restrict__ outb,
                 float* __restrict__ out){
  extern __shared__ char sm[];
  const u32 smb = smem_u32(sm);
  const int tid=threadIdx.x, lane=tid&31, wid=tid>>5;
  const int b0 = blockIdx.x*64;

  // ---- init (all 288 threads) ----
  for(int i=tid;i<19456;i+=288) ((u32*)sm)[i]=0u;  // h tiles
  for(int i=tid;i<2048;i+=288){
    int st_=i>>9, n=i&511, j=n>>2, gt=n&3;
    const float* bp = st_==0?eb0: st_==1?eb1: st_==2?db0: db1;
    ((float*)(sm+BIAS))[i] = bp[gt*128+j];
  }
  for(int i=tid;i<256;i+=288) ((float*)(sm+OUTW))[i]=outWg[i];
  for(int i=tid;i<128;i+=288) ((float*)(sm+PSUM))[i]=0.f;
  if(tid==0){
#pragma unroll
    for(int b=0;b<4;++b){ mbar_init(smb+MBAR+b*8, 32); mbar_init(smb+MBAR+32+b*8, 8); }
  }
  __syncthreads();

  if(wid==8){
    // ================= PRODUCER =================
    int i=0;
    for(int t=0;t<110;++t){
      const int base=(t>=50)?100:0;
      for(int u=0;u<100;++u,++i){
        int b=i&3, r=i>>2;
        if(r>0) mbar_wait(smb+MBAR+32u+(u32)b*8u, (u32)((r&1)^1));
        const char* src=(const char*)g_B + (size_t)(base+u)*8192 + (size_t)lane*16;
        u32 dst=smb+BBUF+(u32)b*8192u+(u32)lane*16u;
#pragma unroll
        for(int c=0;c<16;++c)
          asm volatile("cp.async.cg.shared.global [%0], [%1], 16;"
            ::"r"(dst+(u32)c*512u),"l"(src+(size_t)c*512):"memory");
        // .noinc: the 32 per-thread arrivals count against the init count of 32.
        // (default form pre-increments the expected count -> phase-neutral -> deadlock)
        asm volatile("cp.async.mbarrier.arrive.noinc.shared.b64 [%0];"
          ::"r"(smb+MBAR+(u32)b*8u):"memory");
      }
    }
    return;
  }

  // ================= CONSUMERS (8 warps) =================
  const int wm=wid>>1, wn=wid&1, tq=lane&3;
  const int s = wm*16 + (lane>>2) + (lane&1)*8;
  float c0[32], c1[32]; u32 hst[32];
#pragma unroll
  for(int i=0;i<32;++i){ c0[i]=0.f; c1[i]=0.f; }
  int i=0;

  for(int t=0;t<110;++t){
    const int ph = (t>=50);
    // ---- x into h0 tile cols 128..133 ----
    if(!ph){
      if(tid<64){
        const float* hp = history + (((size_t)(b0+tid)*8)*50 + (size_t)t)*6;
#pragma unroll
        for(int f=0;f<6;++f){
          float v=hp[f];
          __half hh=__float2half_rn(v), hl=__float2half_rn(v-__half2float(hh));
          *(u16*)(sm + H0HI + ((u32)tid*152+128+f)*2) = *(u16*)&hh;
          *(u16*)(sm + H0LO + ((u32)tid*152+128+f)*2) = *(u16*)&hl;
        }
      }
    } else if(t==50){
      if(tid<64){
#pragma unroll
        for(int f=0;f<6;++f){
          float v = (f<2)? start_token[f] : 0.f;
          __half hh=__float2half_rn(v), hl=__float2half_rn(v-__half2float(hh));
          *(u16*)(sm + H0HI + ((u32)tid*152+128+f)*2) = *(u16*)&hh;
          *(u16*)(sm + H0LO + ((u32)tid*152+128+f)*2) = *(u16*)&hl;
        }
      }
    }
    BARC();
    // ---- layer 0 ----
#pragma unroll
    for(int p=0;p<4;++p){
      float acc[8][4];
#pragma unroll
      for(int a=0;a<8;++a){acc[a][0]=0;acc[a][1]=0;acc[a][2]=0;acc[a][3]=0;}
#pragma unroll 1
      for(int kb=0;kb<9;++kb) consume(sm,smb,i,wm,wn,lane, H0HI, kb, acc);
      epi(sm, acc, c0+p*8, hst+p*8, ph*2+0, p, wn, lane, s, false);
    }
    BARC();
#pragma unroll
    for(int p=0;p<4;++p)
#pragma unroll
      for(int nt=0;nt<8;++nt){
        int j = p*32 + wn*16 + nt*2 + (tq>>1);
        u32 v = hst[p*8+nt];
        *(u16*)(sm + H0HI + ((u32)s*152+(u32)j)*2) = (u16)v;
        *(u16*)(sm + H0LO + ((u32)s*152+(u32)j)*2) = (u16)(v>>16);
      }
    BARC();
    // ---- layer 1 ----
#pragma unroll
    for(int p=0;p<4;++p){
      float acc[8][4];
#pragma unroll
      for(int a=0;a<8;++a){acc[a][0]=0;acc[a][1]=0;acc[a][2]=0;acc[a][3]=0;}
#pragma unroll 1
      for(int kq=0;kq<16;++kq) consume(sm,smb,i,wm,wn,lane, (kq<8)?H0HI:H1HI, kq&7, acc);
      epi(sm, acc, c1+p*8, hst+p*8, ph*2+1, p, wn, lane, s, ph!=0);
    }
    BARC();
#pragma unroll
    for(int p=0;p<4;++p)
#pragma unroll
      for(int nt=0;nt<8;++nt){
        int j = p*32 + wn*16 + nt*2 + (tq>>1);
        u32 v = hst[p*8+nt];
        *(u16*)(sm + H1HI + ((u32)s*152+(u32)j)*2) = (u16)v;
        *(u16*)(sm + H1LO + ((u32)s*152+(u32)j)*2) = (u16)(v>>16);
      }
    if(ph){
      BARC();
      if(tid<128){
        int ss=tid>>1, o=tid&1;
        float y = ((float*)(sm+PSUM))[tid] + outb[o];
        out[((size_t)(b0+ss)*60 + (size_t)(t-50))*2 + o] = y;
        ((float*)(sm+PSUM))[tid]=0.f;
        __half hh=__float2half_rn(y), hl=__float2half_rn(y-__half2float(hh));
        *(u16*)(sm + H0HI + ((u32)ss*152+128+(u32)o)*2) = *(u16*)&hh;
        *(u16*)(sm + H0LO + ((u32)ss*152+128+(u32)o)*2) = *(u16*)&hl;
      }
    }
    BARC();
  }
}

extern "C" void kernel_launch(void* const* d_in, const int* in_sizes, int n_in,
                              void* d_out, int out_size){
  const float* history     = (const float*)d_in[0];
  const float* start_token = (const float*)d_in[1];
  const float* eWih0=(const float*)d_in[2],  *eWhh0=(const float*)d_in[3],  *eb0=(const float*)d_in[4];
  const float* eWih1=(const float*)d_in[5],  *eWhh1=(const float*)d_in[6],  *eb1=(const float*)d_in[7];
  const float* dWih0=(const float*)d_in[8],  *dWhh0=(const float*)d_in[9],  *db0=(const float*)d_in[10];
  const float* dWih1=(const float*)d_in[11], *dWhh1=(const float*)d_in[12], *db1=(const float*)d_in[13];
  const float* outW=(const float*)d_in[14],  *outb=(const float*)d_in[15];
  float* out=(float*)d_out;
  (void)in_sizes; (void)n_in; (void)out_size;

  cudaFuncSetAttribute(lstm_hmma_kernel, cudaFuncAttributeMaxDynamicSharedMemorySize, SMSZ);

  prep_kernel<<<200, 256>>>(eWih0,eWhh0,eWih1,eWhh1,dWih0,dWhh0,dWih1,dWhh1);
  lstm_hmma_kernel<<<256, 288, SMSZ>>>(history,start_token,eb0,eb1,db0,db1,outW,outb,out);
}

// round 10
// speedup vs baseline: 2.4960x; 1.1214x over previous
#include <cuda_runtime.h>
#include <cuda_fp16.h>
#include <cstdint>
#include <cstddef>

typedef unsigned int u32; typedef unsigned short u16;

// ---- smem layout (bytes) ----
#define H0HI 0u
#define H0LO 19456u
#define H1HI 38912u
#define H1LO 58368u
#define BBUF 77824u      // 4 x 8192 B-staging ring
#define BIAS 110592u     // 4*512 f32 gate-interleaved
#define OUTW 118784u
#define PSUM 119808u
#define MBAR 120320u     // full[4] @ +0, empty[4] @ +32
#define SMSZ 120448u

// prepped weight stream: 200 units x 8192B, fragment-order:
// unit: [ntblk 0..15][lane 0..31][bh0,bh1,bl0,bl1] (16B per lane)
__device__ uint4 g_B[200 * 512];

__device__ __forceinline__ u32 smem_u32(const void* p){
  u32 a; asm("{ .reg .u64 t; cvta.to.shared.u64 t, %1; cvt.u32.u64 %0, t; }":"=r"(a):"l"(p)); return a;
}
__device__ __forceinline__ float sigm(float v){ return 1.0f/(1.0f+__expf(-v)); }
__device__ __forceinline__ float tanh_(float v){
  float ax=fabsf(v), e=__expf(-2.0f*ax);
  return copysignf(__fdividef(1.0f-e,1.0f+e), v);
}
#define MMA(d,a0,a1,a2,a3,b0,b1) \
  asm volatile("mma.sync.aligned.m16n8k16.row.col.f32.f16.f16.f32 " \
    "{%0,%1,%2,%3},{%4,%5,%6,%7},{%8,%9},{%0,%1,%2,%3};" \
    :"+f"(d[0]),"+f"(d[1]),"+f"(d[2]),"+f"(d[3]) \
    :"r"(a0),"r"(a1),"r"(a2),"r"(a3),"r"(b0),"r"(b1))

__device__ __forceinline__ void mbar_init(u32 mb,u32 c){
  asm volatile("mbarrier.init.shared.b64 [%0], %1;"::"r"(mb),"r"(c):"memory");
}
__device__ __forceinline__ void mbar_wait(u32 mb,u32 ph){
  u32 done;
  asm volatile("{\n\t.reg .pred p;\n\t"
    "mbarrier.try_wait.parity.acquire.cta.shared::cta.b64 p, [%1], %2;\n\t"
    "selp.b32 %0, 1, 0, p;\n\t}":"=r"(done):"r"(mb),"r"(ph):"memory");
  if(!done){
    asm volatile("{\n\t.reg .pred P1;\n\tWL_%=:\n\t"
      "mbarrier.try_wait.parity.acquire.cta.shared::cta.b64 P1, [%0], %1, 0x989680;\n\t"
      "@P1 bra.uni WD_%=;\n\tbra.uni WL_%=;\n\tWD_%=:\n\t}"::"r"(mb),"r"(ph):"memory");
  }
}
#define BARC() asm volatile("bar.sync 1, 512;":::"memory")   // 16 consumer warps

// ===== prep: fragment-order fp16 hi/lo weight stream (layout unchanged) =====
__global__ void prep_kernel(const float* eWih0,const float* eWhh0,const float* eWih1,const float* eWhh1,
                            const float* dWih0,const float* dWhh0,const float* dWih1,const float* dWhh1){
  int gu=blockIdx.x, ph=gu/100, u=gu%100;
  const float* Wx = ph? dWih0 : eWih0;
  const float* M=nullptr; int nf=ph?2:6, kb=0, isx=0, p;
  if(u<36){ p=u/9; int q9=u%9; M=ph?dWhh0:eWhh0; if(q9==8) isx=1; else kb=q9; }
  else { int v=u-36; p=v/16; int kq=v%16;
         if(kq<8){ M=ph?dWih1:eWih1; kb=kq; } else { M=ph?dWhh1:eWhh1; kb=kq-8; } }
  u32* dst = (u32*)g_B + (size_t)gu*2048;
  for(int e=threadIdx.x; e<2048; e+=256){
    int nt=e>>7, lane=(e>>2)&31, q=e&3;
    int g=lane>>2, tq=lane&3;
    int n_loc=nt*8+g, k_loc=tq*2+(q&1)*8, lo=(q>=2);
    int ng=p*128+n_loc, j=ng>>2, gt=ng&3, wr=gt*128+j;
    float w0=0.f, w1=0.f;
    if(isx){
      if(k_loc<nf)   w0=Wx[wr*nf+k_loc];
      if(k_loc+1<nf) w1=Wx[wr*nf+k_loc+1];
    } else {
      w0=M[wr*128+kb*16+k_loc]; w1=M[wr*128+kb*16+k_loc+1];
    }
    __half h0=__float2half_rn(w0), h1=__float2half_rn(w1);
    u16 o0,o1;
    if(!lo){ o0=*(u16*)&h0; o1=*(u16*)&h1; }
    else{ __half l0=__float2half_rn(w0-__half2float(h0)), l1=__float2half_rn(w1-__half2float(h1));
          o0=*(u16*)&l0; o1=*(u16*)&l1; }
    dst[e] = (u32)o0 | ((u32)o1<<16);
  }
}

// ===== consumer: one unit of MMA (4 nt-blocks per warp) =====
__device__ __forceinline__ void unitmma(char* sm, u32 ahi, int akb, int buf,
                                        int wm,int wn,int lane, float (&acc)[4][4]){
  int g=lane>>2, tq=lane&3;
  u32 ao = ahi + (u32)(((wm*16+g)*152 + akb*16 + tq*2)*2);
  u32 a0=*(u32*)(sm+ao),       a1=*(u32*)(sm+ao+2432);
  u32 a2=*(u32*)(sm+ao+16),    a3=*(u32*)(sm+ao+2448);
  u32 l0=*(u32*)(sm+ao+19456), l1=*(u32*)(sm+ao+21888);
  u32 l2=*(u32*)(sm+ao+19472), l3=*(u32*)(sm+ao+21904);
  u32 bb = BBUF + (u32)buf*8192u + (u32)((wn*4)*32+lane)*16u;
#pragma unroll
  for(int nt=0;nt<4;++nt){
    uint4 bv = *(uint4*)(sm + bb + (u32)nt*512u);
    MMA(acc[nt], a0,a1,a2,a3, bv.x,bv.y);
    MMA(acc[nt], l0,l1,l2,l3, bv.x,bv.y);
    MMA(acc[nt], a0,a1,a2,a3, bv.z,bv.w);
  }
}
__device__ __forceinline__ void consume(char* sm,u32 smb,int& i,int wm,int wn,int lane,
                                        u32 ahi,int akb,float (&acc)[4][4]){
  int b=i&3, r=i>>2; ++i;
  mbar_wait(smb+MBAR+(u32)b*8u, (u32)(r&1));
  unitmma(sm, ahi, akb, b, wm,wn,lane, acc);
  __syncwarp();
  if(lane==0)
    asm volatile("mbarrier.arrive.shared.b64 _, [%0];"::"r"(smb+MBAR+32u+(u32)b*8u):"memory");
}

// ===== epilogue for one 128-n pass (warp covers 32 n -> 8 j) =====
__device__ __forceinline__ void epi(char* sm, float (&acc)[4][4], float* cb, u32* hb,
                                    int set, int p, int wn, int lane, int s, bool proj){
  int tq=lane&3, odd=lane&1;
  const float* bs = (const float*)(sm+BIAS) + set*512 + p*128 + wn*32;
  const float* ow = (const float*)(sm+OUTW);
  float y0=0.f, y1=0.f;
#pragma unroll
  for(int nt=0;nt<4;++nt){
    float s0 = odd? acc[nt][0]:acc[nt][2];
    float s1 = odd? acc[nt][1]:acc[nt][3];
    float r0 = __shfl_xor_sync(0xffffffffu, s0, 1);
    float r1 = __shfl_xor_sync(0xffffffffu, s1, 1);
    float gi = odd? r0 : acc[nt][0];
    float gf = odd? r1 : acc[nt][1];
    float gg = odd? acc[nt][2] : r0;
    float go = odd? acc[nt][3] : r1;
    float4 bv = *(const float4*)(bs + nt*8 + (tq>>1)*4);
    gi+=bv.x; gf+=bv.y; gg+=bv.z; go+=bv.w;
    float c = sigm(gf)*cb[nt] + sigm(gi)*tanh_(gg);
    cb[nt]=c;
    float h = sigm(go)*tanh_(c);
    __half hh=__float2half_rn(h);
    __half hl=__float2half_rn(h-__half2float(hh));
    hb[nt] = (u32)(*(u16*)&hh) | ((u32)(*(u16*)&hl)<<16);
    if(proj){ int j = p*32 + wn*8 + nt*2 + (tq>>1); y0 += h*ow[j]; y1 += h*ow[128+j]; }
  }
  if(proj){ float* ps=(float*)(sm+PSUM); atomicAdd(ps+s*2,y0); atomicAdd(ps+s*2+1,y1); }
}

__global__ void __launch_bounds__(544,1)
lstm_hmma_kernel(const float* __restrict__ history, const float* __restrict__ start_token,
                 const float* __restrict__ eb0, const float* __restrict__ eb1,
                 const float* __restrict__ db0, const float* __restrict__ db1,
                 const float* __restrict__ outWg, const float* __restrict__ outb,
                 float* __restrict__ out){
  extern __shared__ char sm[];
  const u32 smb = smem_u32(sm);
  const int tid=threadIdx.x, lane=tid&31, wid=tid>>5;
  const int b0 = blockIdx.x*64;

  // ---- init (all 544 threads) ----
  for(int i=tid;i<19456;i+=544) ((u32*)sm)[i]=0u;  // h tiles
  for(int i=tid;i<2048;i+=544){
    int st_=i>>9, n=i&511, j=n>>2, gt=n&3;
    const float* bp = st_==0?eb0: st_==1?eb1: st_==2?db0: db1;
    ((float*)(sm+BIAS))[i] = bp[gt*128+j];
  }
  for(int i=tid;i<256;i+=544) ((float*)(sm+OUTW))[i]=outWg[i];
  for(int i=tid;i<128;i+=544) ((float*)(sm+PSUM))[i]=0.f;
  if(tid==0){
#pragma unroll
    for(int b=0;b<4;++b){ mbar_init(smb+MBAR+b*8, 32); mbar_init(smb+MBAR+32+b*8, 16); }
  }
  __syncthreads();

  if(wid==16){
    // ================= PRODUCER =================
    int i=0;
    for(int t=0;t<110;++t){
      const int base=(t>=50)?100:0;
      for(int u=0;u<100;++u,++i){
        int b=i&3, r=i>>2;
        if(r>0) mbar_wait(smb+MBAR+32u+(u32)b*8u, (u32)((r&1)^1));
        const char* src=(const char*)g_B + (size_t)(base+u)*8192 + (size_t)lane*16;
        u32 dst=smb+BBUF+(u32)b*8192u+(u32)lane*16u;
#pragma unroll
        for(int c=0;c<16;++c)
          asm volatile("cp.async.cg.shared.global [%0], [%1], 16;"
            ::"r"(dst+(u32)c*512u),"l"(src+(size_t)c*512):"memory");
        asm volatile("cp.async.mbarrier.arrive.noinc.shared.b64 [%0];"
          ::"r"(smb+MBAR+(u32)b*8u):"memory");
      }
    }
    return;
  }

  // ================= CONSUMERS (16 warps: wm 0..3, wn 0..3) =================
  const int wm=wid>>2, wn=wid&3, tq=lane&3;
  const int s = wm*16 + (lane>>2) + (lane&1)*8;
  float c0[16], c1[16]; u32 hst[16];
#pragma unroll
  for(int i=0;i<16;++i){ c0[i]=0.f; c1[i]=0.f; }
  int i=0;

  for(int t=0;t<110;++t){
    const int ph = (t>=50);
    // ---- x into h0 tile cols 128..133 ----
    if(!ph){
      if(tid<64){
        const float* hp = history + (((size_t)(b0+tid)*8)*50 + (size_t)t)*6;
#pragma unroll
        for(int f=0;f<6;++f){
          float v=hp[f];
          __half hh=__float2half_rn(v), hl=__float2half_rn(v-__half2float(hh));
          *(u16*)(sm + H0HI + ((u32)tid*152+128+f)*2) = *(u16*)&hh;
          *(u16*)(sm + H0LO + ((u32)tid*152+128+f)*2) = *(u16*)&hl;
        }
      }
    } else if(t==50){
      if(tid<64){
#pragma unroll
        for(int f=0;f<6;++f){
          float v = (f<2)? start_token[f] : 0.f;
          __half hh=__float2half_rn(v), hl=__float2half_rn(v-__half2float(hh));
          *(u16*)(sm + H0HI + ((u32)tid*152+128+f)*2) = *(u16*)&hh;
          *(u16*)(sm + H0LO + ((u32)tid*152+128+f)*2) = *(u16*)&hl;
        }
      }
    }
    BARC();
    // ---- layer 0 ----
#pragma unroll
    for(int p=0;p<4;++p){
      float acc[4][4];
#pragma unroll
      for(int a=0;a<4;++a){acc[a][0]=0;acc[a][1]=0;acc[a][2]=0;acc[a][3]=0;}
#pragma unroll 1
      for(int kb=0;kb<9;++kb) consume(sm,smb,i,wm,wn,lane, H0HI, kb, acc);
      epi(sm, acc, c0+p*4, hst+p*4, ph*2+0, p, wn, lane, s, false);
    }
    BARC();
#pragma unroll
    for(int p=0;p<4;++p)
#pragma unroll
      for(int nt=0;nt<4;++nt){
        int j = p*32 + wn*8 + nt*2 + (tq>>1);
        u32 v = hst[p*4+nt];
        *(u16*)(sm + H0HI + ((u32)s*152+(u32)j)*2) = (u16)v;
        *(u16*)(sm + H0LO + ((u32)s*152+(u32)j)*2) = (u16)(v>>16);
      }
    BARC();
    // ---- layer 1 ----
#pragma unroll
    for(int p=0;p<4;++p){
      float acc[4][4];
#pragma unroll
      for(int a=0;a<4;++a){acc[a][0]=0;acc[a][1]=0;acc[a][2]=0;acc[a][3]=0;}
#pragma unroll 1
      for(int kq=0;kq<16;++kq) consume(sm,smb,i,wm,wn,lane, (kq<8)?H0HI:H1HI, kq&7, acc);
      epi(sm, acc, c1+p*4, hst+p*4, ph*2+1, p, wn, lane, s, ph!=0);
    }
    BARC();
#pragma unroll
    for(int p=0;p<4;++p)
#pragma unroll
      for(int nt=0;nt<4;++nt){
        int j = p*32 + wn*8 + nt*2 + (tq>>1);
        u32 v = hst[p*4+nt];
        *(u16*)(sm + H1HI + ((u32)s*152+(u32)j)*2) = (u16)v;
        *(u16*)(sm + H1LO + ((u32)s*152+(u32)j)*2) = (u16)(v>>16);
      }
    if(ph){
      BARC();
      if(tid<128){
        int ss=tid>>1, o=tid&1;
        float y = ((float*)(sm+PSUM))[tid] + outb[o];
        out[((size_t)(b0+ss)*60 + (size_t)(t-50))*2 + o] = y;
        ((float*)(sm+PSUM))[tid]=0.f;
        __half hh=__float2half_rn(y), hl=__float2half_rn(y-__half2float(hh));
        *(u16*)(sm + H0HI + ((u32)ss*152+128+(u32)o)*2) = *(u16*)&hh;
        *(u16*)(sm + H0LO + ((u32)ss*152+128+(u32)o)*2) = *(u16*)&hl;
      }
    }
    BARC();
  }
}

extern "C" void kernel_launch(void* const* d_in, const int* in_sizes, int n_in,
                              void* d_out, int out_size){
  const float* history     = (const float*)d_in[0];
  const float* start_token = (const float*)d_in[1];
  const float* eWih0=(const float*)d_in[2],  *eWhh0=(const float*)d_in[3],  *eb0=(const float*)d_in[4];
  const float* eWih1=(const float*)d_in[5],  *eWhh1=(const float*)d_in[6],  *eb1=(const float*)d_in[7];
  const float* dWih0=(const float*)d_in[8],  *dWhh0=(const float*)d_in[9],  *db0=(const float*)d_in[10];
  const float* dWih1=(const float*)d_in[11], *dWhh1=(const float*)d_in[12], *db1=(const float*)d_in[13];
  const float* outW=(const float*)d_in[14],  *outb=(const float*)d_in[15];
  float* out=(float*)d_out;
  (void)in_sizes; (void)n_in; (void)out_size;

  cudaFuncSetAttribute(lstm_hmma_kernel, cudaFuncAttributeMaxDynamicSharedMemorySize, SMSZ);

  prep_kernel<<<200, 256>>>(eWih0,eWhh0,eWih1,eWhh1,dWih0,dWhh0,dWih1,dWhh1);
  lstm_hmma_kernel<<<256, 544, SMSZ>>>(history,start_token,eb0,eb1,db0,db1,outW,outb,out);
}

// round 11
// speedup vs baseline: 2.5537x; 1.0231x over previous
#include <cuda_runtime.h>
#include <cuda_fp16.h>
#include <cstdint>
#include <cstddef>

typedef unsigned int u32; typedef unsigned short u16;

// ---- smem layout (bytes) ----
// h0 block: [hi_buf0][hi_buf1][lo_buf0][lo_buf1], tile 64x152 halfs (x in cols 128..133)
// h1 block: same structure, tile 64x136 halfs
#define H0OFF  0u
#define H0SZ   19456u
#define H0LOD  38912u      // lo = hi + 38912
#define H1OFF  77824u
#define H1SZ   17408u
#define H1LOD  34816u
#define BBUF   147456u     // 4 x 16384 slot ring
#define BIAS   212992u     // 4*512 f32 gate-interleaved
#define OUTW   221184u
#define PSUM   222208u
#define MBAR   222720u     // full[4]@+0, empty[4]@+32
#define SMSZ   222784u

// weight stream: 100 slots (50/phase) x 16KB; slot = [unit p_even 8KB][unit p_odd 8KB]
// unit internal: [ntblk 0..15][lane 0..31][bh0,bh1,bl0,bl1] 16B/lane
__device__ uint4 g_B[100 * 1024];

__device__ __forceinline__ u32 smem_u32(const void* p){
  u32 a; asm("{ .reg .u64 t; cvta.to.shared.u64 t, %1; cvt.u32.u64 %0, t; }":"=r"(a):"l"(p)); return a;
}
__device__ __forceinline__ float sigm(float v){ return 1.0f/(1.0f+__expf(-v)); }
__device__ __forceinline__ float tanh_(float v){
  float ax=fabsf(v), e=__expf(-2.0f*ax);
  return copysignf(__fdividef(1.0f-e,1.0f+e), v);
}
#define MMA(d,a0,a1,a2,a3,b0,b1) \
  asm volatile("mma.sync.aligned.m16n8k16.row.col.f32.f16.f16.f32 " \
    "{%0,%1,%2,%3},{%4,%5,%6,%7},{%8,%9},{%0,%1,%2,%3};" \
    :"+f"(d[0]),"+f"(d[1]),"+f"(d[2]),"+f"(d[3]) \
    :"r"(a0),"r"(a1),"r"(a2),"r"(a3),"r"(b0),"r"(b1))

__device__ __forceinline__ void mbar_init(u32 mb,u32 c){
  asm volatile("mbarrier.init.shared.b64 [%0], %1;"::"r"(mb),"r"(c):"memory");
}
__device__ __forceinline__ void mbar_wait(u32 mb,u32 ph){
  u32 done;
  asm volatile("{\n\t.reg .pred p;\n\t"
    "mbarrier.try_wait.parity.acquire.cta.shared::cta.b64 p, [%1], %2;\n\t"
    "selp.b32 %0, 1, 0, p;\n\t}":"=r"(done):"r"(mb),"r"(ph):"memory");
  if(!done){
    asm volatile("{\n\t.reg .pred P1;\n\tWL_%=:\n\t"
      "mbarrier.try_wait.parity.acquire.cta.shared::cta.b64 P1, [%0], %1, 0x989680;\n\t"
      "@P1 bra.uni WD_%=;\n\tbra.uni WL_%=;\n\tWD_%=:\n\t}"::"r"(mb),"r"(ph):"memory");
  }
}
#define BARC() asm volatile("bar.sync 1, 512;":::"memory")

// ===== prep: same fragment math as R9, remapped into paired slots =====
__global__ void prep_kernel(const float* eWih0,const float* eWhh0,const float* eWih1,const float* eWhh1,
                            const float* dWih0,const float* dWhh0,const float* dWih1,const float* dWhh1){
  int gu=blockIdx.x, ph=gu/100, u=gu%100;
  const float* Wx = ph? dWih0 : eWih0;
  const float* M=nullptr; int nf=ph?2:6, kb=0, isx=0, p;
  if(u<36){ p=u/9; int q9=u%9; M=ph?dWhh0:eWhh0; if(q9==8) isx=1; else kb=q9; }
  else { int v=u-36; p=v/16; int kq=v%16;
         if(kq<8){ M=ph?dWih1:eWih1; kb=kq; } else { M=ph?dWhh1:eWhh1; kb=kq-8; } }
  // slot remap
  int slot, half;
  if(u<36){ int pp=p>>1, q9=u%9; slot=pp*9+q9; half=p&1; }
  else     { int v=u-36, pp=(v/16)>>1, kq=v%16; slot=18+pp*16+kq; half=(v/16)&1; }
  u32* dst = (u32*)g_B + ((size_t)(ph*50+slot)*2 + half)*2048;
  for(int e=threadIdx.x; e<2048; e+=256){
    int nt=e>>7, lane=(e>>2)&31, q=e&3;
    int g=lane>>2, tq=lane&3;
    int n_loc=nt*8+g, k_loc=tq*2+(q&1)*8, lo=(q>=2);
    int ng=p*128+n_loc, j=ng>>2, gt=ng&3, wr=gt*128+j;
    float w0=0.f, w1=0.f;
    if(isx){
      if(k_loc<nf)   w0=Wx[wr*nf+k_loc];
      if(k_loc+1<nf) w1=Wx[wr*nf+k_loc+1];
    } else {
      w0=M[wr*128+kb*16+k_loc]; w1=M[wr*128+kb*16+k_loc+1];
    }
    __half h0=__float2half_rn(w0), h1=__float2half_rn(w1);
    u16 o0,o1;
    if(!lo){ o0=*(u16*)&h0; o1=*(u16*)&h1; }
    else{ __half l0=__float2half_rn(w0-__half2float(h0)), l1=__float2half_rn(w1-__half2float(h1));
          o0=*(u16*)&l0; o1=*(u16*)&l1; }
    dst[e] = (u32)o0 | ((u32)o1<<16);
  }
}

// ===== consumer: one slot = 2 units (shared kb, p-pair) =====
__device__ __forceinline__ void cslot(char* sm,u32 smb,int& i,u32 boff,
                                      u32 abase_off,u32 aoff,u32 lood,int akb,int lane,
                                      float (&A2)[2][4][4]){
  int b=i&3, r=i>>2; ++i;
  mbar_wait(smb+MBAR+(u32)b*8u, (u32)(r&1));
  u32 aaddr = smb + abase_off + aoff + (u32)akb*32u;
  u32 a0,a1,a2,a3,l0,l1,l2,l3;
  asm volatile("ldmatrix.sync.aligned.m8n8.x4.shared.b16 {%0,%1,%2,%3},[%4];"
    :"=r"(a0),"=r"(a1),"=r"(a2),"=r"(a3):"r"(aaddr));
  asm volatile("ldmatrix.sync.aligned.m8n8.x4.shared.b16 {%0,%1,%2,%3},[%4];"
    :"=r"(l0),"=r"(l1),"=r"(l2),"=r"(l3):"r"(aaddr+lood));
  u32 bslot = BBUF + (u32)b*16384u + boff;
#pragma unroll
  for(int u=0;u<2;++u){
#pragma unroll
    for(int nt=0;nt<4;++nt){
      uint4 bv = *(uint4*)(sm + bslot + (u32)u*8192u + (u32)nt*512u);
      MMA(A2[u][nt], a0,a1,a2,a3, bv.x,bv.y);
      MMA(A2[u][nt], l0,l1,l2,l3, bv.x,bv.y);
      MMA(A2[u][nt], a0,a1,a2,a3, bv.z,bv.w);
    }
  }
  __syncwarp();
  if(lane==0)
    asm volatile("mbarrier.arrive.shared.b64 _, [%0];"::"r"(smb+MBAR+32u+(u32)b*8u):"memory");
}

// ===== epilogue: gates -> c,h ; h' written straight to write-buffer =====
__device__ __forceinline__ void epi(char* sm, float (&acc)[4][4], float* cb,
                                    int set, int p, int wn, int lane, int s, bool proj,
                                    u32 hw_off, u32 lood, int str){
  int tq=lane&3, odd=lane&1;
  const float* bs = (const float*)(sm+BIAS) + set*512 + p*128 + wn*32;
  const float* ow = (const float*)(sm+OUTW);
  float y0=0.f, y1=0.f;
#pragma unroll
  for(int nt=0;nt<4;++nt){
    float s0 = odd? acc[nt][0]:acc[nt][2];
    float s1 = odd? acc[nt][1]:acc[nt][3];
    float r0 = __shfl_xor_sync(0xffffffffu, s0, 1);
    float r1 = __shfl_xor_sync(0xffffffffu, s1, 1);
    float gi = odd? r0 : acc[nt][0];
    float gf = odd? r1 : acc[nt][1];
    float gg = odd? acc[nt][2] : r0;
    float go = odd? acc[nt][3] : r1;
    float4 bv = *(const float4*)(bs + nt*8 + (tq>>1)*4);
    gi+=bv.x; gf+=bv.y; gg+=bv.z; go+=bv.w;
    float c = sigm(gf)*cb[nt] + sigm(gi)*tanh_(gg);
    cb[nt]=c;
    float h = sigm(go)*tanh_(c);
    __half hh=__float2half_rn(h);
    __half hl=__float2half_rn(h-__half2float(hh));
    int j = p*32 + wn*8 + nt*2 + (tq>>1);
    u32 off = hw_off + (u32)(s*str + j)*2u;
    *(u16*)(sm+off)      = *(u16*)&hh;
    *(u16*)(sm+off+lood) = *(u16*)&hl;
    if(proj){ y0 += h*ow[j]; y1 += h*ow[128+j]; }
  }
  if(proj){ float* ps=(float*)(sm+PSUM); atomicAdd(ps+s*2,y0); atomicAdd(ps+s*2+1,y1); }
}

__global__ void __launch_bounds__(544,1)
lstm_hmma_kernel(const float* __restrict__ history, const float* __restrict__ start_token,
                 const float* __restrict__ eb0, const float* __restrict__ eb1,
                 const float* __restrict__ db0, const float* __restrict__ db1,
                 const float* __restrict__ outWg, const float* __restrict__ outb,
                 float* __restrict__ out){
  extern __shared__ char sm[];
  const u32 smb = smem_u32(sm);
  const int tid=threadIdx.x, lane=tid&31, wid=tid>>5;
  const int b0 = blockIdx.x*64;

  // ---- init ----
  for(u32 i=tid;i<BBUF/4u;i+=544) ((u32*)sm)[i]=0u;   // all h tiles (both buffers)
  for(int i=tid;i<2048;i+=544){
    int st_=i>>9, n=i&511, j=n>>2, gt=n&3;
    const float* bp = st_==0?eb0: st_==1?eb1: st_==2?db0: db1;
    ((float*)(sm+BIAS))[i] = bp[gt*128+j];
  }
  for(int i=tid;i<256;i+=544) ((float*)(sm+OUTW))[i]=outWg[i];
  for(int i=tid;i<128;i+=544) ((float*)(sm+PSUM))[i]=0.f;
  if(tid<64){  // x(0) into read-buffer 0 of h0
    const float* hp = history + (((size_t)(b0+tid)*8)*50)*6;
#pragma unroll
    for(int f=0;f<6;++f){
      float v=hp[f];
      __half hh=__float2half_rn(v), hl=__float2half_rn(v-__half2float(hh));
      u32 off = H0OFF + (u32)(tid*152+128+f)*2u;
      *(u16*)(sm+off)=*(u16*)&hh; *(u16*)(sm+off+H0LOD)=*(u16*)&hl;
    }
  }
  if(tid==0){
#pragma unroll
    for(int b=0;b<4;++b){ mbar_init(smb+MBAR+b*8, 32); mbar_init(smb+MBAR+32+b*8, 16); }
  }
  __syncthreads();

  if(wid==16){
    // ================= PRODUCER =================
    int i=0;
    for(int t=0;t<110;++t){
      const int pb=(t>=50)?50:0;
      for(int s=0;s<50;++s,++i){
        int b=i&3, r=i>>2;
        if(r>0) mbar_wait(smb+MBAR+32u+(u32)b*8u, (u32)((r&1)^1));
        const char* src=(const char*)g_B + (size_t)(pb+s)*16384 + (size_t)lane*16;
        u32 dst=smb+BBUF+(u32)b*16384u+(u32)lane*16u;
#pragma unroll
        for(int c=0;c<32;++c)
          asm volatile("cp.async.cg.shared.global [%0], [%1], 16;"
            ::"r"(dst+(u32)c*512u),"l"(src+(size_t)c*512):"memory");
        asm volatile("cp.async.mbarrier.arrive.noinc.shared.b64 [%0];"
          ::"r"(smb+MBAR+(u32)b*8u):"memory");
      }
    }
    return;
  }

  // ================= CONSUMERS (16 warps) =================
  const int wm=wid>>2, wn=wid&3, tq=lane&3;
  const int s = wm*16 + (lane>>2) + (lane&1)*8;
  // ldmatrix per-thread address parts
  const int lr=lane&7, seg=lane>>3;
  const int rowb = wm*16 + lr + (seg&1)*8;
  const int kpart = (seg>>1)*8;
  const u32 aoff152 = (u32)(rowb*152 + kpart)*2u;
  const u32 aoff136 = (u32)(rowb*136 + kpart)*2u;
  const u32 boff = (u32)(wn*128 + lane)*16u;

  float c0[16], c1[16];
#pragma unroll
  for(int i=0;i<16;++i){ c0[i]=0.f; c1[i]=0.f; }
  int i=0;
  const float st0=start_token[0], st1=start_token[1];

  for(int t=0;t<110;++t){
    const int ph=(t>=50), rw=t&1;
    const u32 h0r = H0OFF + (u32)rw*H0SZ, h0w = H0OFF + (u32)(rw^1)*H0SZ;
    const u32 h1r = H1OFF + (u32)rw*H1SZ, h1w = H1OFF + (u32)(rw^1)*H1SZ;
    // ---- layer 0: 18 slots ----
#pragma unroll
    for(int pp=0;pp<2;++pp){
      float A2[2][4][4];
#pragma unroll
      for(int u=0;u<2;++u)
#pragma unroll
        for(int a=0;a<4;++a){A2[u][a][0]=0;A2[u][a][1]=0;A2[u][a][2]=0;A2[u][a][3]=0;}
#pragma unroll 1
      for(int kb=0;kb<9;++kb) cslot(sm,smb,i,boff, h0r, aoff152, H0LOD, kb, lane, A2);
      epi(sm, A2[0], c0+(2*pp+0)*4, ph*2+0, 2*pp+0, wn, lane, s, false, h0w, H0LOD, 152);
      epi(sm, A2[1], c0+(2*pp+1)*4, ph*2+0, 2*pp+1, wn, lane, s, false, h0w, H0LOD, 152);
    }
    BARC();
    // ---- layer 1: 32 slots ----
#pragma unroll
    for(int pp=0;pp<2;++pp){
      float A2[2][4][4];
#pragma unroll
      for(int u=0;u<2;++u)
#pragma unroll
        for(int a=0;a<4;++a){A2[u][a][0]=0;A2[u][a][1]=0;A2[u][a][2]=0;A2[u][a][3]=0;}
#pragma unroll 1
      for(int kq=0;kq<16;++kq){
        if(kq<8) cslot(sm,smb,i,boff, h0w, aoff152, H0LOD, kq,   lane, A2);
        else     cslot(sm,smb,i,boff, h1r, aoff136, H1LOD, kq-8, lane, A2);
      }
      epi(sm, A2[0], c1+(2*pp+0)*4, ph*2+1, 2*pp+0, wn, lane, s, ph!=0, h1w, H1LOD, 136);
      epi(sm, A2[1], c1+(2*pp+1)*4, ph*2+1, 2*pp+1, wn, lane, s, ph!=0, h1w, H1LOD, 136);
    }
    // ---- tail ----
    if(!ph){
      if(tid<64){   // x(t+1) -> h0 write-buffer (next step's read buffer)
        float xv[6];
        if(t+1<50){
          const float* hp = history + (((size_t)(b0+tid)*8)*50 + (size_t)(t+1))*6;
#pragma unroll
          for(int f=0;f<6;++f) xv[f]=hp[f];
        } else { xv[0]=st0; xv[1]=st1; xv[2]=0; xv[3]=0; xv[4]=0; xv[5]=0; }
#pragma unroll
        for(int f=0;f<6;++f){
          __half hh=__float2half_rn(xv[f]), hl=__float2half_rn(xv[f]-__half2float(hh));
          u32 off = h0w + (u32)(tid*152+128+f)*2u;
          *(u16*)(sm+off)=*(u16*)&hh; *(u16*)(sm+off+H0LOD)=*(u16*)&hl;
        }
      }
      BARC();
    } else {
      BARC();
      if(tid<128){
        int ss=tid>>1, o=tid&1;
        float y = ((float*)(sm+PSUM))[tid] + outb[o];
        out[((size_t)(b0+ss)*60 + (size_t)(t-50))*2 + o] = y;
        ((float*)(sm+PSUM))[tid]=0.f;
        __half hh=__float2half_rn(y), hl=__float2half_rn(y-__half2float(hh));
        u32 off = h0w + (u32)(ss*152+128+o)*2u;
        *(u16*)(sm+off)=*(u16*)&hh; *(u16*)(sm+off+H0LOD)=*(u16*)&hl;
      }
      BARC();
    }
  }
}

extern "C" void kernel_launch(void* const* d_in, const int* in_sizes, int n_in,
                              void* d_out, int out_size){
  const float* history     = (const float*)d_in[0];
  const float* start_token = (const float*)d_in[1];
  const float* eWih0=(const float*)d_in[2],  *eWhh0=(const float*)d_in[3],  *eb0=(const float*)d_in[4];
  const float* eWih1=(const float*)d_in[5],  *eWhh1=(const float*)d_in[6],  *eb1=(const float*)d_in[7];
  const float* dWih0=(const float*)d_in[8],  *dWhh0=(const float*)d_in[9],  *db0=(const float*)d_in[10];
  const float* dWih1=(const float*)d_in[11], *dWhh1=(const float*)d_in[12], *db1=(const float*)d_in[13];
  const float* outW=(const float*)d_in[14],  *outb=(const float*)d_in[15];
  float* out=(float*)d_out;
  (void)in_sizes; (void)n_in; (void)out_size;

  cudaFuncSetAttribute(lstm_hmma_kernel, cudaFuncAttributeMaxDynamicSharedMemorySize, SMSZ);

  prep_kernel<<<200, 256>>>(eWih0,eWhh0,eWih1,eWhh1,dWih0,dWhh0,dWih1,dWhh1);
  lstm_hmma_kernel<<<256, 544, SMSZ>>>(history,start_token,eb0,eb1,db0,db1,outW,outb,out);
}

// round 12
// speedup vs baseline: 3.4050x; 1.3333x over previous
#include <cuda_runtime.h>
#include <cuda_fp16.h>
#include <cstdint>
#include <cstddef>

typedef unsigned int u32; typedef unsigned short u16;

// ---- smem layout (bytes) ----
#define H0OFF  0u
#define H0SZ   19456u
#define H0LOD  38912u
#define H1OFF  77824u
#define H1SZ   17408u
#define H1LOD  34816u
#define BBUF   147456u     // 8 x 8192 slot ring
#define BIAS   212992u
#define OUTW   221184u
#define PSUM   222208u
#define MBAR   222720u     // full[8]@+0, empty[8]@+64
#define SMSZ   222848u

// weight stream: 100 slots x 8KB; slot = [unit p_even 4KB][unit p_odd 4KB]
// unit: [ntblk 0..15][lane 0..31][bh0,bh1] 8B/lane  (B = fp16 hi only)
__device__ uint4 g_B[100 * 512];

__device__ __forceinline__ u32 smem_u32(const void* p){
  u32 a; asm("{ .reg .u64 t; cvta.to.shared.u64 t, %1; cvt.u32.u64 %0, t; }":"=r"(a):"l"(p)); return a;
}
__device__ __forceinline__ float sigm(float v){ return 1.0f/(1.0f+__expf(-v)); }
__device__ __forceinline__ float tanh_(float v){
  float ax=fabsf(v), e=__expf(-2.0f*ax);
  return copysignf(__fdividef(1.0f-e,1.0f+e), v);
}
#define MMA(d,a0,a1,a2,a3,b0,b1) \
  asm volatile("mma.sync.aligned.m16n8k16.row.col.f32.f16.f16.f32 " \
    "{%0,%1,%2,%3},{%4,%5,%6,%7},{%8,%9},{%0,%1,%2,%3};" \
    :"+f"(d[0]),"+f"(d[1]),"+f"(d[2]),"+f"(d[3]) \
    :"r"(a0),"r"(a1),"r"(a2),"r"(a3),"r"(b0),"r"(b1))

__device__ __forceinline__ void mbar_init(u32 mb,u32 c){
  asm volatile("mbarrier.init.shared.b64 [%0], %1;"::"r"(mb),"r"(c):"memory");
}
__device__ __forceinline__ void mbar_wait(u32 mb,u32 ph){
  u32 done;
  asm volatile("{\n\t.reg .pred p;\n\t"
    "mbarrier.try_wait.parity.acquire.cta.shared::cta.b64 p, [%1], %2;\n\t"
    "selp.b32 %0, 1, 0, p;\n\t}":"=r"(done):"r"(mb),"r"(ph):"memory");
  if(!done){
    asm volatile("{\n\t.reg .pred P1;\n\tWL_%=:\n\t"
      "mbarrier.try_wait.parity.acquire.cta.shared::cta.b64 P1, [%0], %1, 0x989680;\n\t"
      "@P1 bra.uni WD_%=;\n\tbra.uni WL_%=;\n\tWD_%=:\n\t}"::"r"(mb),"r"(ph):"memory");
  }
}
#define BARC() asm volatile("bar.sync 1, 512;":::"memory")

// ===== prep: fp16-hi B fragments, paired slots (same remap as R10) =====
__global__ void prep_kernel(const float* eWih0,const float* eWhh0,const float* eWih1,const float* eWhh1,
                            const float* dWih0,const float* dWhh0,const float* dWih1,const float* dWhh1){
  int gu=blockIdx.x, ph=gu/100, u=gu%100;
  const float* Wx = ph? dWih0 : eWih0;
  const float* M=nullptr; int nf=ph?2:6, kb=0, isx=0, p;
  if(u<36){ p=u/9; int q9=u%9; M=ph?dWhh0:eWhh0; if(q9==8) isx=1; else kb=q9; }
  else { int v=u-36; p=v/16; int kq=v%16;
         if(kq<8){ M=ph?dWih1:eWih1; kb=kq; } else { M=ph?dWhh1:eWhh1; kb=kq-8; } }
  int slot, half;
  if(u<36){ int pp=p>>1, q9=u%9; slot=pp*9+q9; half=p&1; }
  else     { int v=u-36, pp=(v/16)>>1, kq=v%16; slot=18+pp*16+kq; half=(v/16)&1; }
  u32* dst = (u32*)g_B + ((size_t)(ph*50+slot)*2 + half)*1024;
  for(int e=threadIdx.x; e<1024; e+=256){
    int nt=e>>6, lane=(e>>1)&31, q=e&1;
    int g=lane>>2, tq=lane&3;
    int n_loc=nt*8+g, k_loc=tq*2+q*8;
    int ng=p*128+n_loc, j=ng>>2, gt=ng&3, wr=gt*128+j;
    float w0=0.f, w1=0.f;
    if(isx){
      if(k_loc<nf)   w0=Wx[wr*nf+k_loc];
      if(k_loc+1<nf) w1=Wx[wr*nf+k_loc+1];
    } else {
      w0=M[wr*128+kb*16+k_loc]; w1=M[wr*128+kb*16+k_loc+1];
    }
    __half h0=__float2half_rn(w0), h1=__float2half_rn(w1);
    dst[e] = (u32)(*(u16*)&h0) | ((u32)(*(u16*)&h1)<<16);
  }
}

// ===== consumer: one slot = 2 units (shared kb, p-pair), 2-term =====
__device__ __forceinline__ void cslot(char* sm,u32 smb,int& i,u32 boff,
                                      u32 abase_off,u32 aoff,u32 lood,int akb,int lane,
                                      float (&A2)[2][4][4]){
  int b=i&7, r=i>>3; ++i;
  mbar_wait(smb+MBAR+(u32)b*8u, (u32)(r&1));
  u32 aaddr = smb + abase_off + aoff + (u32)akb*32u;
  u32 a0,a1,a2,a3,l0,l1,l2,l3;
  asm volatile("ldmatrix.sync.aligned.m8n8.x4.shared.b16 {%0,%1,%2,%3},[%4];"
    :"=r"(a0),"=r"(a1),"=r"(a2),"=r"(a3):"r"(aaddr));
  asm volatile("ldmatrix.sync.aligned.m8n8.x4.shared.b16 {%0,%1,%2,%3},[%4];"
    :"=r"(l0),"=r"(l1),"=r"(l2),"=r"(l3):"r"(aaddr+lood));
  u32 bslot = BBUF + (u32)b*8192u + boff;
#pragma unroll
  for(int u=0;u<2;++u){
#pragma unroll
    for(int nt=0;nt<4;++nt){
      uint2 bv = *(uint2*)(sm + bslot + (u32)u*4096u + (u32)nt*256u);
      MMA(A2[u][nt], a0,a1,a2,a3, bv.x,bv.y);
      MMA(A2[u][nt], l0,l1,l2,l3, bv.x,bv.y);
    }
  }
  __syncwarp();
  if(lane==0)
    asm volatile("mbarrier.arrive.shared.b64 _, [%0];"::"r"(smb+MBAR+64u+(u32)b*8u):"memory");
}

// ===== epilogue =====
__device__ __forceinline__ void epi(char* sm, float (&acc)[4][4], float* cb,
                                    int set, int p, int wn, int lane, int s, bool proj,
                                    u32 hw_off, u32 lood, int str){
  int tq=lane&3, odd=lane&1;
  const float* bs = (const float*)(sm+BIAS) + set*512 + p*128 + wn*32;
  const float* ow = (const float*)(sm+OUTW);
  float y0=0.f, y1=0.f;
#pragma unroll
  for(int nt=0;nt<4;++nt){
    float s0 = odd? acc[nt][0]:acc[nt][2];
    float s1 = odd? acc[nt][1]:acc[nt][3];
    float r0 = __shfl_xor_sync(0xffffffffu, s0, 1);
    float r1 = __shfl_xor_sync(0xffffffffu, s1, 1);
    float gi = odd? r0 : acc[nt][0];
    float gf = odd? r1 : acc[nt][1];
    float gg = odd? acc[nt][2] : r0;
    float go = odd? acc[nt][3] : r1;
    float4 bv = *(const float4*)(bs + nt*8 + (tq>>1)*4);
    gi+=bv.x; gf+=bv.y; gg+=bv.z; go+=bv.w;
    float c = sigm(gf)*cb[nt] + sigm(gi)*tanh_(gg);
    cb[nt]=c;
    float h = sigm(go)*tanh_(c);
    __half hh=__float2half_rn(h);
    __half hl=__float2half_rn(h-__half2float(hh));
    int j = p*32 + wn*8 + nt*2 + (tq>>1);
    u32 off = hw_off + (u32)(s*str + j)*2u;
    *(u16*)(sm+off)      = *(u16*)&hh;
    *(u16*)(sm+off+lood) = *(u16*)&hl;
    if(proj){ y0 += h*ow[j]; y1 += h*ow[128+j]; }
  }
  if(proj){ float* ps=(float*)(sm+PSUM); atomicAdd(ps+s*2,y0); atomicAdd(ps+s*2+1,y1); }
}

__global__ void __launch_bounds__(544,1)
lstm_hmma_kernel(const float* __restrict__ history, const float* __restrict__ start_token,
                 const float* __restrict__ eb0, const float* __restrict__ eb1,
                 const float* __restrict__ db0, const float* __restrict__ db1,
                 const float* __restrict__ outWg, const float* __restrict__ outb,
                 float* __restrict__ out){
  extern __shared__ char sm[];
  const u32 smb = smem_u32(sm);
  const int tid=threadIdx.x, lane=tid&31, wid=tid>>5;
  const int b0 = blockIdx.x*64;

  // ---- init ----
  for(u32 i=tid;i<BBUF/4u;i+=544) ((u32*)sm)[i]=0u;
  for(int i=tid;i<2048;i+=544){
    int st_=i>>9, n=i&511, j=n>>2, gt=n&3;
    const float* bp = st_==0?eb0: st_==1?eb1: st_==2?db0: db1;
    ((float*)(sm+BIAS))[i] = bp[gt*128+j];
  }
  for(int i=tid;i<256;i+=544) ((float*)(sm+OUTW))[i]=outWg[i];
  for(int i=tid;i<128;i+=544) ((float*)(sm+PSUM))[i]=0.f;
  if(tid<64){  // x(0) into read-buffer 0 of h0
    const float* hp = history + (((size_t)(b0+tid)*8)*50)*6;
#pragma unroll
    for(int f=0;f<6;++f){
      float v=hp[f];
      __half hh=__float2half_rn(v), hl=__float2half_rn(v-__half2float(hh));
      u32 off = H0OFF + (u32)(tid*152+128+f)*2u;
      *(u16*)(sm+off)=*(u16*)&hh; *(u16*)(sm+off+H0LOD)=*(u16*)&hl;
    }
  }
  if(tid==0){
#pragma unroll
    for(int b=0;b<8;++b){ mbar_init(smb+MBAR+b*8, 32); mbar_init(smb+MBAR+64+b*8, 16); }
  }
  __syncthreads();

  if(wid==16){
    // ================= PRODUCER =================
    int i=0;
    for(int t=0;t<110;++t){
      const int pb=(t>=50)?50:0;
      for(int s=0;s<50;++s,++i){
        int b=i&7, r=i>>3;
        if(r>0) mbar_wait(smb+MBAR+64u+(u32)b*8u, (u32)((r&1)^1));
        const char* src=(const char*)g_B + (size_t)(pb+s)*8192 + (size_t)lane*16;
        u32 dst=smb+BBUF+(u32)b*8192u+(u32)lane*16u;
#pragma unroll
        for(int c=0;c<16;++c)
          asm volatile("cp.async.cg.shared.global [%0], [%1], 16;"
            ::"r"(dst+(u32)c*512u),"l"(src+(size_t)c*512):"memory");
        asm volatile("cp.async.mbarrier.arrive.noinc.shared.b64 [%0];"
          ::"r"(smb+MBAR+(u32)b*8u):"memory");
      }
    }
    return;
  }

  // ================= CONSUMERS (16 warps) =================
  const int wm=wid>>2, wn=wid&3, tq=lane&3;
  const int s = wm*16 + (lane>>2) + (lane&1)*8;
  const int lr=lane&7, seg=lane>>3;
  const int rowb = wm*16 + lr + (seg&1)*8;
  const int kpart = (seg>>1)*8;
  const u32 aoff152 = (u32)(rowb*152 + kpart)*2u;
  const u32 aoff136 = (u32)(rowb*136 + kpart)*2u;
  const u32 boff = (u32)(wn*128 + lane)*8u;

  float c0[16], c1[16];
#pragma unroll
  for(int i=0;i<16;++i){ c0[i]=0.f; c1[i]=0.f; }
  int i=0;
  const float st0=start_token[0], st1=start_token[1];

  for(int t=0;t<110;++t){
    const int ph=(t>=50), rw=t&1;
    const u32 h0r = H0OFF + (u32)rw*H0SZ, h0w = H0OFF + (u32)(rw^1)*H0SZ;
    const u32 h1r = H1OFF + (u32)rw*H1SZ, h1w = H1OFF + (u32)(rw^1)*H1SZ;
    // ---- layer 0: 18 slots ----
#pragma unroll
    for(int pp=0;pp<2;++pp){
      float A2[2][4][4];
#pragma unroll
      for(int u=0;u<2;++u)
#pragma unroll
        for(int a=0;a<4;++a){A2[u][a][0]=0;A2[u][a][1]=0;A2[u][a][2]=0;A2[u][a][3]=0;}
#pragma unroll 1
      for(int kb=0;kb<9;++kb) cslot(sm,smb,i,boff, h0r, aoff152, H0LOD, kb, lane, A2);
      epi(sm, A2[0], c0+(2*pp+0)*4, ph*2+0, 2*pp+0, wn, lane, s, false, h0w, H0LOD, 152);
      epi(sm, A2[1], c0+(2*pp+1)*4, ph*2+0, 2*pp+1, wn, lane, s, false, h0w, H0LOD, 152);
    }
    BARC();
    // ---- layer 1: 32 slots ----
#pragma unroll
    for(int pp=0;pp<2;++pp){
      float A2[2][4][4];
#pragma unroll
      for(int u=0;u<2;++u)
#pragma unroll
        for(int a=0;a<4;++a){A2[u][a][0]=0;A2[u][a][1]=0;A2[u][a][2]=0;A2[u][a][3]=0;}
#pragma unroll 1
      for(int kq=0;kq<16;++kq){
        if(kq<8) cslot(sm,smb,i,boff, h0w, aoff152, H0LOD, kq,   lane, A2);
        else     cslot(sm,smb,i,boff, h1r, aoff136, H1LOD, kq-8, lane, A2);
      }
      epi(sm, A2[0], c1+(2*pp+0)*4, ph*2+1, 2*pp+0, wn, lane, s, ph!=0, h1w, H1LOD, 136);
      epi(sm, A2[1], c1+(2*pp+1)*4, ph*2+1, 2*pp+1, wn, lane, s, ph!=0, h1w, H1LOD, 136);
    }
    // ---- tail ----
    if(!ph){
      if(tid<64){
        float xv[6];
        if(t+1<50){
          const float* hp = history + (((size_t)(b0+tid)*8)*50 + (size_t)(t+1))*6;
#pragma unroll
          for(int f=0;f<6;++f) xv[f]=hp[f];
        } else { xv[0]=st0; xv[1]=st1; xv[2]=0; xv[3]=0; xv[4]=0; xv[5]=0; }
#pragma unroll
        for(int f=0;f<6;++f){
          __half hh=__float2half_rn(xv[f]), hl=__float2half_rn(xv[f]-__half2float(hh));
          u32 off = h0w + (u32)(tid*152+128+f)*2u;
          *(u16*)(sm+off)=*(u16*)&hh; *(u16*)(sm+off+H0LOD)=*(u16*)&hl;
        }
      }
      BARC();
    } else {
      BARC();
      if(tid<128){
        int ss=tid>>1, o=tid&1;
        float y = ((float*)(sm+PSUM))[tid] + outb[o];
        out[((size_t)(b0+ss)*60 + (size_t)(t-50))*2 + o] = y;
        ((float*)(sm+PSUM))[tid]=0.f;
        __half hh=__float2half_rn(y), hl=__float2half_rn(y-__half2float(hh));
        u32 off = h0w + (u32)(ss*152+128+o)*2u;
        *(u16*)(sm+off)=*(u16*)&hh; *(u16*)(sm+off+H0LOD)=*(u16*)&hl;
      }
      BARC();
    }
  }
}

extern "C" void kernel_launch(void* const* d_in, const int* in_sizes, int n_in,
                              void* d_out, int out_size){
  const float* history     = (const float*)d_in[0];
  const float* start_token = (const float*)d_in[1];
  const float* eWih0=(const float*)d_in[2],  *eWhh0=(const float*)d_in[3],  *eb0=(const float*)d_in[4];
  const float* eWih1=(const float*)d_in[5],  *eWhh1=(const float*)d_in[6],  *eb1=(const float*)d_in[7];
  const float* dWih0=(const float*)d_in[8],  *dWhh0=(const float*)d_in[9],  *db0=(const float*)d_in[10];
  const float* dWih1=(const float*)d_in[11], *dWhh1=(const float*)d_in[12], *db1=(const float*)d_in[13];
  const float* outW=(const float*)d_in[14],  *outb=(const float*)d_in[15];
  float* out=(float*)d_out;
  (void)in_sizes; (void)n_in; (void)out_size;

  cudaFuncSetAttribute(lstm_hmma_kernel, cudaFuncAttributeMaxDynamicSharedMemorySize, SMSZ);

  prep_kernel<<<200, 256>>>(eWih0,eWhh0,eWih1,eWhh1,dWih0,dWhh0,dWih1,dWhh1);
  lstm_hmma_kernel<<<256, 544, SMSZ>>>(history,start_token,eb0,eb1,db0,db1,outW,outb,out);
}

// round 13
// speedup vs baseline: 4.1191x; 1.2097x over previous
#include <cuda_runtime.h>
#include <cuda_fp16.h>
#include <cstdint>
#include <cstddef>

typedef unsigned int u32; typedef unsigned short u16;

// ---- smem layout (bytes) ----
#define H0OFF  0u
#define H0SZ   19456u
#define H0LOD  38912u
#define H1OFF  77824u
#define H1SZ   17408u
#define H1LOD  34816u
#define BBUF   147456u     // 4 x 16384 slot ring
#define BIAS   212992u
#define OUTW   221184u
#define PSUM   222208u
#define MBAR   222720u     // full[4]@+0, empty[4]@+32
#define SMSZ   222784u

// weight stream: per phase 26 slots x 16KB; slot = 4 x 4KB sub-units:
//   [kkA p_even][kkA p_odd][kkB p_even][kkB p_odd]
// sub-unit: [ntblk 0..15][lane 0..31][bh0,bh1] 8B/lane (fp16 hi only)
__device__ uint4 g_B[2 * 26 * 1024];

__device__ __forceinline__ u32 smem_u32(const void* p){
  u32 a; asm("{ .reg .u64 t; cvta.to.shared.u64 t, %1; cvt.u32.u64 %0, t; }":"=r"(a):"l"(p)); return a;
}
__device__ __forceinline__ float sigm(float v){
  return __fdividef(1.0f, 1.0f+__expf(-v));
}
__device__ __forceinline__ float tanh_(float v){
  float ax=fabsf(v), e=__expf(-2.0f*ax);
  return copysignf(__fdividef(1.0f-e,1.0f+e), v);
}
#define MMA(d,a0,a1,a2,a3,b0,b1) \
  asm volatile("mma.sync.aligned.m16n8k16.row.col.f32.f16.f16.f32 " \
    "{%0,%1,%2,%3},{%4,%5,%6,%7},{%8,%9},{%0,%1,%2,%3};" \
    :"+f"(d[0]),"+f"(d[1]),"+f"(d[2]),"+f"(d[3]) \
    :"r"(a0),"r"(a1),"r"(a2),"r"(a3),"r"(b0),"r"(b1))

__device__ __forceinline__ void mbar_init(u32 mb,u32 c){
  asm volatile("mbarrier.init.shared.b64 [%0], %1;"::"r"(mb),"r"(c):"memory");
}
__device__ __forceinline__ void mbar_wait(u32 mb,u32 ph){
  u32 done;
  asm volatile("{\n\t.reg .pred p;\n\t"
    "mbarrier.try_wait.parity.acquire.cta.shared::cta.b64 p, [%1], %2;\n\t"
    "selp.b32 %0, 1, 0, p;\n\t}":"=r"(done):"r"(mb),"r"(ph):"memory");
  if(!done){
    asm volatile("{\n\t.reg .pred P1;\n\tWL_%=:\n\t"
      "mbarrier.try_wait.parity.acquire.cta.shared::cta.b64 P1, [%0], %1, 0x989680;\n\t"
      "@P1 bra.uni WD_%=;\n\tbra.uni WL_%=;\n\tWD_%=:\n\t}"::"r"(mb),"r"(ph):"memory");
  }
}
#define BARC() asm volatile("bar.sync 1, 512;":::"memory")

// ===== prep: 208 blocks = 2 phases x 26 slots x 4 sub-units =====
__global__ void prep_kernel(const float* eWih0,const float* eWhh0,const float* eWih1,const float* eWhh1,
                            const float* dWih0,const float* dWhh0,const float* dWih1,const float* dWhh1){
  int gu=blockIdx.x, ph=gu/104, r=gu%104, s=r/4, m=r%4;
  int kk=m>>1, half=m&1;
  const float* Wx = ph? dWih0 : eWih0; int nf = ph?2:6;
  const float* M=nullptr; int p, kb=0, isx=0, isz=0;
  if(s<10){
    int pp=s/5, sl=s%5; p=pp*2+half;
    if(sl<4){ M = ph?dWhh0:eWhh0; kb = 2*sl+kk; }
    else { if(kk==0) isx=1; else isz=1; }
  } else {
    int v=s-10, pp=v/8, pr=v%8; p=pp*2+half;
    int kq=2*pr+kk;
    if(kq<8){ M=ph?dWih1:eWih1; kb=kq; } else { M=ph?dWhh1:eWhh1; kb=kq-8; }
  }
  u32* dst=(u32*)g_B + (((size_t)(ph*26+s))*4 + (size_t)m)*1024;
  for(int e=threadIdx.x;e<1024;e+=256){
    int nt=e>>6, lane=(e>>1)&31, q=e&1;
    int g=lane>>2, tq=lane&3;
    int n_loc=nt*8+g, k_loc=tq*2+q*8;
    int ng=p*128+n_loc, j=ng>>2, gt=ng&3, wr=gt*128+j;
    float w0=0.f, w1=0.f;
    if(isz){ /* zero pad */ }
    else if(isx){
      if(k_loc<nf)   w0=Wx[wr*nf+k_loc];
      if(k_loc+1<nf) w1=Wx[wr*nf+k_loc+1];
    } else {
      w0=M[wr*128+kb*16+k_loc]; w1=M[wr*128+kb*16+k_loc+1];
    }
    __half h0=__float2half_rn(w0), h1=__float2half_rn(w1);
    dst[e] = (u32)(*(u16*)&h0) | ((u32)(*(u16*)&h1)<<16);
  }
}

// ===== consumer: one 16KB slot = 2 kb x 2 units, 2-term =====
__device__ __forceinline__ void cslot2(char* sm,u32 smb,int& i,u32 boff,
                                       u32 abase_off,u32 aoff,u32 lood,int akb0,int lane,
                                       float (&A2)[2][4][4]){
  int b=i&3, r=i>>2; ++i;
  mbar_wait(smb+MBAR+(u32)b*8u, (u32)(r&1));
  u32 bslot = BBUF + (u32)b*16384u + boff;
#pragma unroll
  for(int kk=0;kk<2;++kk){
    u32 aaddr = smb + abase_off + aoff + (u32)(akb0+kk)*32u;
    u32 a0,a1,a2,a3,l0,l1,l2,l3;
    asm volatile("ldmatrix.sync.aligned.m8n8.x4.shared.b16 {%0,%1,%2,%3},[%4];"
      :"=r"(a0),"=r"(a1),"=r"(a2),"=r"(a3):"r"(aaddr));
    asm volatile("ldmatrix.sync.aligned.m8n8.x4.shared.b16 {%0,%1,%2,%3},[%4];"
      :"=r"(l0),"=r"(l1),"=r"(l2),"=r"(l3):"r"(aaddr+lood));
#pragma unroll
    for(int u=0;u<2;++u){
#pragma unroll
      for(int nt=0;nt<4;++nt){
        uint2 bv = *(uint2*)(sm + bslot + (u32)kk*8192u + (u32)u*4096u + (u32)nt*256u);
        MMA(A2[u][nt], a0,a1,a2,a3, bv.x,bv.y);
        MMA(A2[u][nt], l0,l1,l2,l3, bv.x,bv.y);
      }
    }
  }
  __syncwarp();
  if(lane==0)
    asm volatile("mbarrier.arrive.shared.b64 _, [%0];"::"r"(smb+MBAR+32u+(u32)b*8u):"memory");
}

// ===== epilogue =====
__device__ __forceinline__ void epi(char* sm, float (&acc)[4][4], float* cb,
                                    int set, int p, int wn, int lane, int s, bool proj,
                                    u32 hw_off, u32 lood, int str){
  int tq=lane&3, odd=lane&1;
  const float* bs = (const float*)(sm+BIAS) + set*512 + p*128 + wn*32;
  const float* ow = (const float*)(sm+OUTW);
  float y0=0.f, y1=0.f;
#pragma unroll
  for(int nt=0;nt<4;++nt){
    float s0 = odd? acc[nt][0]:acc[nt][2];
    float s1 = odd? acc[nt][1]:acc[nt][3];
    float r0 = __shfl_xor_sync(0xffffffffu, s0, 1);
    float r1 = __shfl_xor_sync(0xffffffffu, s1, 1);
    float gi = odd? r0 : acc[nt][0];
    float gf = odd? r1 : acc[nt][1];
    float gg = odd? acc[nt][2] : r0;
    float go = odd? acc[nt][3] : r1;
    float4 bv = *(const float4*)(bs + nt*8 + (tq>>1)*4);
    gi+=bv.x; gf+=bv.y; gg+=bv.z; go+=bv.w;
    float c = sigm(gf)*cb[nt] + sigm(gi)*tanh_(gg);
    cb[nt]=c;
    float h = sigm(go)*tanh_(c);
    __half hh=__float2half_rn(h);
    __half hl=__float2half_rn(h-__half2float(hh));
    int j = p*32 + wn*8 + nt*2 + (tq>>1);
    u32 off = hw_off + (u32)(s*str + j)*2u;
    *(u16*)(sm+off)      = *(u16*)&hh;
    *(u16*)(sm+off+lood) = *(u16*)&hl;
    if(proj){ y0 += h*ow[j]; y1 += h*ow[128+j]; }
  }
  if(proj){ float* ps=(float*)(sm+PSUM); atomicAdd(ps+s*2,y0); atomicAdd(ps+s*2+1,y1); }
}

__global__ void __launch_bounds__(544,1)
lstm_hmma_kernel(const float* __restrict__ history, const float* __restrict__ start_token,
                 const float* __restrict__ eb0, const float* __restrict__ eb1,
                 const float* __restrict__ db0, const float* __restrict__ db1,
                 const float* __restrict__ outWg, const float* __restrict__ outb,
                 float* __restrict__ out){
  extern __shared__ char sm[];
  const u32 smb = smem_u32(sm);
  const int tid=threadIdx.x, lane=tid&31, wid=tid>>5;
  const int b0 = blockIdx.x*64;

  // ---- init ----
  for(u32 i=tid;i<BBUF/4u;i+=544) ((u32*)sm)[i]=0u;
  for(int i=tid;i<2048;i+=544){
    int st_=i>>9, n=i&511, j=n>>2, gt=n&3;
    const float* bp = st_==0?eb0: st_==1?eb1: st_==2?db0: db1;
    ((float*)(sm+BIAS))[i] = bp[gt*128+j];
  }
  for(int i=tid;i<256;i+=544) ((float*)(sm+OUTW))[i]=outWg[i];
  for(int i=tid;i<128;i+=544) ((float*)(sm+PSUM))[i]=0.f;
  if(tid<64){  // x(0) into read-buffer 0 of h0
    const float* hp = history + (((size_t)(b0+tid)*8)*50)*6;
#pragma unroll
    for(int f=0;f<6;++f){
      float v=hp[f];
      __half hh=__float2half_rn(v), hl=__float2half_rn(v-__half2float(hh));
      u32 off = H0OFF + (u32)(tid*152+128+f)*2u;
      *(u16*)(sm+off)=*(u16*)&hh; *(u16*)(sm+off+H0LOD)=*(u16*)&hl;
    }
  }
  if(tid==0){
#pragma unroll
    for(int b=0;b<4;++b){ mbar_init(smb+MBAR+b*8, 32); mbar_init(smb+MBAR+32+b*8, 16); }
  }
  __syncthreads();

  if(wid==16){
    // ================= PRODUCER =================
    int i=0;
    for(int t=0;t<110;++t){
      const int pb=(t>=50)?26:0;
      for(int s=0;s<26;++s,++i){
        int b=i&3, r=i>>2;
        if(r>0) mbar_wait(smb+MBAR+32u+(u32)b*8u, (u32)((r&1)^1));
        const char* src=(const char*)g_B + (size_t)(pb+s)*16384 + (size_t)lane*16;
        u32 dst=smb+BBUF+(u32)b*16384u+(u32)lane*16u;
#pragma unroll
        for(int c=0;c<32;++c)
          asm volatile("cp.async.cg.shared.global [%0], [%1], 16;"
            ::"r"(dst+(u32)c*512u),"l"(src+(size_t)c*512):"memory");
        asm volatile("cp.async.mbarrier.arrive.noinc.shared.b64 [%0];"
          ::"r"(smb+MBAR+(u32)b*8u):"memory");
      }
    }
    return;
  }

  // ================= CONSUMERS (16 warps) =================
  const int wm=wid>>2, wn=wid&3, tq=lane&3;
  const int s = wm*16 + (lane>>2) + (lane&1)*8;
  const int lr=lane&7, seg=lane>>3;
  const int rowb = wm*16 + lr + (seg&1)*8;
  const int kpart = (seg>>1)*8;
  const u32 aoff152 = (u32)(rowb*152 + kpart)*2u;
  const u32 aoff136 = (u32)(rowb*136 + kpart)*2u;
  const u32 boff = (u32)(wn*128 + lane)*8u;

  float c0[16], c1[16];
#pragma unroll
  for(int i=0;i<16;++i){ c0[i]=0.f; c1[i]=0.f; }
  int i=0;
  const float st0=start_token[0], st1=start_token[1];

  for(int t=0;t<110;++t){
    const int ph=(t>=50), rw=t&1;
    const u32 h0r = H0OFF + (u32)rw*H0SZ, h0w = H0OFF + (u32)(rw^1)*H0SZ;
    const u32 h1r = H1OFF + (u32)rw*H1SZ, h1w = H1OFF + (u32)(rw^1)*H1SZ;
    // ---- layer 0: 10 slots (5 per p-pair; slot 4 = x + zero pad) ----
#pragma unroll
    for(int pp=0;pp<2;++pp){
      float A2[2][4][4];
#pragma unroll
      for(int u=0;u<2;++u)
#pragma unroll
        for(int a=0;a<4;++a){A2[u][a][0]=0;A2[u][a][1]=0;A2[u][a][2]=0;A2[u][a][3]=0;}
#pragma unroll 1
      for(int sl=0;sl<5;++sl)
        cslot2(sm,smb,i,boff, h0r, aoff152, H0LOD, 2*sl, lane, A2);
      epi(sm, A2[0], c0+(2*pp+0)*4, ph*2+0, 2*pp+0, wn, lane, s, false, h0w, H0LOD, 152);
      epi(sm, A2[1], c0+(2*pp+1)*4, ph*2+0, 2*pp+1, wn, lane, s, false, h0w, H0LOD, 152);
    }
    BARC();
    // ---- layer 1: 16 slots (8 per p-pair) ----
#pragma unroll
    for(int pp=0;pp<2;++pp){
      float A2[2][4][4];
#pragma unroll
      for(int u=0;u<2;++u)
#pragma unroll
        for(int a=0;a<4;++a){A2[u][a][0]=0;A2[u][a][1]=0;A2[u][a][2]=0;A2[u][a][3]=0;}
#pragma unroll 1
      for(int pr=0;pr<8;++pr){
        if(pr<4) cslot2(sm,smb,i,boff, h0w, aoff152, H0LOD, 2*pr,   lane, A2);
        else     cslot2(sm,smb,i,boff, h1r, aoff136, H1LOD, 2*pr-8, lane, A2);
      }
      epi(sm, A2[0], c1+(2*pp+0)*4, ph*2+1, 2*pp+0, wn, lane, s, ph!=0, h1w, H1LOD, 136);
      epi(sm, A2[1], c1+(2*pp+1)*4, ph*2+1, 2*pp+1, wn, lane, s, ph!=0, h1w, H1LOD, 136);
    }
    // ---- tail ----
    if(!ph){
      if(tid<64){
        float xv[6];
        if(t+1<50){
          const float* hp = history + (((size_t)(b0+tid)*8)*50 + (size_t)(t+1))*6;
#pragma unroll
          for(int f=0;f<6;++f) xv[f]=hp[f];
        } else { xv[0]=st0; xv[1]=st1; xv[2]=0; xv[3]=0; xv[4]=0; xv[5]=0; }
#pragma unroll
        for(int f=0;f<6;++f){
          __half hh=__float2half_rn(xv[f]), hl=__float2half_rn(xv[f]-__half2float(hh));
          u32 off = h0w + (u32)(tid*152+128+f)*2u;
          *(u16*)(sm+off)=*(u16*)&hh; *(u16*)(sm+off+H0LOD)=*(u16*)&hl;
        }
      }
      BARC();
    } else {
      BARC();
      if(tid<128){
        int ss=tid>>1, o=tid&1;
        float y = ((float*)(sm+PSUM))[tid] + outb[o];
        out[((size_t)(b0+ss)*60 + (size_t)(t-50))*2 + o] = y;
        ((float*)(sm+PSUM))[tid]=0.f;
        __half hh=__float2half_rn(y), hl=__float2half_rn(y-__half2float(hh));
        u32 off = h0w + (u32)(ss*152+128+o)*2u;
        *(u16*)(sm+off)=*(u16*)&hh; *(u16*)(sm+off+H0LOD)=*(u16*)&hl;
      }
      BARC();
    }
  }
}

extern "C" void kernel_launch(void* const* d_in, const int* in_sizes, int n_in,
                              void* d_out, int out_size){
  const float* history     = (const float*)d_in[0];
  const float* start_token = (const float*)d_in[1];
  const float* eWih0=(const float*)d_in[2],  *eWhh0=(const float*)d_in[3],  *eb0=(const float*)d_in[4];
  const float* eWih1=(const float*)d_in[5],  *eWhh1=(const float*)d_in[6],  *eb1=(const float*)d_in[7];
  const float* dWih0=(const float*)d_in[8],  *dWhh0=(const float*)d_in[9],  *db0=(const float*)d_in[10];
  const float* dWih1=(const float*)d_in[11], *dWhh1=(const float*)d_in[12], *db1=(const float*)d_in[13];
  const float* outW=(const float*)d_in[14],  *outb=(const float*)d_in[15];
  float* out=(float*)d_out;
  (void)in_sizes; (void)n_in; (void)out_size;

  cudaFuncSetAttribute(lstm_hmma_kernel, cudaFuncAttributeMaxDynamicSharedMemorySize, SMSZ);

  prep_kernel<<<208, 256>>>(eWih0,eWhh0,eWih1,eWhh1,dWih0,dWhh0,dWih1,dWhh1);
  lstm_hmma_kernel<<<256, 544, SMSZ>>>(history,start_token,eb0,eb1,db0,db1,outW,outb,out);
}

// round 14
// speedup vs baseline: 5.4575x; 1.3249x over previous
#include <cuda_runtime.h>
#include <cuda_fp16.h>
#include <cstdint>
#include <cstddef>

typedef unsigned int u32; typedef unsigned short u16;

// ---- smem layout (bytes) ----
#define H0OFF  0u
#define H0SZ   19456u
#define H1OFF  77824u
#define H1SZ   17408u
#define BBUF   147456u     // 4 x 16384 slot ring
#define BIAS   212992u
#define OUTW   221184u
#define PSUM   222208u
#define MBAR   222720u     // full[4]@+0, empty[4]@+32
#define SMSZ   222784u

// weight stream: per phase 26 slots x 16KB; slot = 4 x 4KB sub-units:
//   [kkA p_even][kkA p_odd][kkB p_even][kkB p_odd]
// sub-unit: [ntblk 0..15][lane 0..31][bh0,bh1] 8B/lane (fp16 hi only)
__device__ uint4 g_B[2 * 26 * 1024];

__device__ __forceinline__ u32 smem_u32(const void* p){
  u32 a; asm("{ .reg .u64 t; cvta.to.shared.u64 t, %1; cvt.u32.u64 %0, t; }":"=r"(a):"l"(p)); return a;
}
__device__ __forceinline__ float sigm(float v){
  return __fdividef(1.0f, 1.0f+__expf(-v));
}
__device__ __forceinline__ float tanh_(float v){
  float ax=fabsf(v), e=__expf(-2.0f*ax);
  return copysignf(__fdividef(1.0f-e,1.0f+e), v);
}
#define MMA(d,a0,a1,a2,a3,b0,b1) \
  asm volatile("mma.sync.aligned.m16n8k16.row.col.f32.f16.f16.f32 " \
    "{%0,%1,%2,%3},{%4,%5,%6,%7},{%8,%9},{%0,%1,%2,%3};" \
    :"+f"(d[0]),"+f"(d[1]),"+f"(d[2]),"+f"(d[3]) \
    :"r"(a0),"r"(a1),"r"(a2),"r"(a3),"r"(b0),"r"(b1))

__device__ __forceinline__ void mbar_init(u32 mb,u32 c){
  asm volatile("mbarrier.init.shared.b64 [%0], %1;"::"r"(mb),"r"(c):"memory");
}
__device__ __forceinline__ void mbar_wait(u32 mb,u32 ph){
  u32 done;
  asm volatile("{\n\t.reg .pred p;\n\t"
    "mbarrier.try_wait.parity.acquire.cta.shared::cta.b64 p, [%1], %2;\n\t"
    "selp.b32 %0, 1, 0, p;\n\t}":"=r"(done):"r"(mb),"r"(ph):"memory");
  if(!done){
    asm volatile("{\n\t.reg .pred P1;\n\tWL_%=:\n\t"
      "mbarrier.try_wait.parity.acquire.cta.shared::cta.b64 P1, [%0], %1, 0x989680;\n\t"
      "@P1 bra.uni WD_%=;\n\tbra.uni WL_%=;\n\tWD_%=:\n\t}"::"r"(mb),"r"(ph):"memory");
  }
}
#define BARC() asm volatile("bar.sync 1, 512;":::"memory")

// ===== prep: 208 blocks = 2 phases x 26 slots x 4 sub-units (unchanged) =====
__global__ void prep_kernel(const float* eWih0,const float* eWhh0,const float* eWih1,const float* eWhh1,
                            const float* dWih0,const float* dWhh0,const float* dWih1,const float* dWhh1){
  int gu=blockIdx.x, ph=gu/104, r=gu%104, s=r/4, m=r%4;
  int kk=m>>1, half=m&1;
  const float* Wx = ph? dWih0 : eWih0; int nf = ph?2:6;
  const float* M=nullptr; int p, kb=0, isx=0, isz=0;
  if(s<10){
    int pp=s/5, sl=s%5; p=pp*2+half;
    if(sl<4){ M = ph?dWhh0:eWhh0; kb = 2*sl+kk; }
    else { if(kk==0) isx=1; else isz=1; }
  } else {
    int v=s-10, pp=v/8, pr=v%8; p=pp*2+half;
    int kq=2*pr+kk;
    if(kq<8){ M=ph?dWih1:eWih1; kb=kq; } else { M=ph?dWhh1:eWhh1; kb=kq-8; }
  }
  u32* dst=(u32*)g_B + (((size_t)(ph*26+s))*4 + (size_t)m)*1024;
  for(int e=threadIdx.x;e<1024;e+=256){
    int nt=e>>6, lane=(e>>1)&31, q=e&1;
    int g=lane>>2, tq=lane&3;
    int n_loc=nt*8+g, k_loc=tq*2+q*8;
    int ng=p*128+n_loc, j=ng>>2, gt=ng&3, wr=gt*128+j;
    float w0=0.f, w1=0.f;
    if(isz){ /* zero pad */ }
    else if(isx){
      if(k_loc<nf)   w0=Wx[wr*nf+k_loc];
      if(k_loc+1<nf) w1=Wx[wr*nf+k_loc+1];
    } else {
      w0=M[wr*128+kb*16+k_loc]; w1=M[wr*128+kb*16+k_loc+1];
    }
    __half h0=__float2half_rn(w0), h1=__float2half_rn(w1);
    dst[e] = (u32)(*(u16*)&h0) | ((u32)(*(u16*)&h1)<<16);
  }
}

// ===== consumer: one 16KB slot = 2 kb x 2 units, SINGLE-term (h hi only) =====
__device__ __forceinline__ void cslot2(char* sm,u32 smb,int& i,u32 boff,
                                       u32 abase_off,u32 aoff,int akb0,int lane,
                                       float (&A2)[2][4][4]){
  int b=i&3, r=i>>2; ++i;
  mbar_wait(smb+MBAR+(u32)b*8u, (u32)(r&1));
  u32 bslot = BBUF + (u32)b*16384u + boff;
#pragma unroll
  for(int kk=0;kk<2;++kk){
    u32 aaddr = smb + abase_off + aoff + (u32)(akb0+kk)*32u;
    u32 a0,a1,a2,a3;
    asm volatile("ldmatrix.sync.aligned.m8n8.x4.shared.b16 {%0,%1,%2,%3},[%4];"
      :"=r"(a0),"=r"(a1),"=r"(a2),"=r"(a3):"r"(aaddr));
#pragma unroll
    for(int u=0;u<2;++u){
#pragma unroll
      for(int nt=0;nt<4;++nt){
        uint2 bv = *(uint2*)(sm + bslot + (u32)kk*8192u + (u32)u*4096u + (u32)nt*256u);
        MMA(A2[u][nt], a0,a1,a2,a3, bv.x,bv.y);
      }
    }
  }
  __syncwarp();
  if(lane==0)
    asm volatile("mbarrier.arrive.shared.b64 _, [%0];"::"r"(smb+MBAR+32u+(u32)b*8u):"memory");
}

// ===== epilogue (h stored fp16-hi only) =====
__device__ __forceinline__ void epi(char* sm, float (&acc)[4][4], float* cb,
                                    int set, int p, int wn, int lane, int s, bool proj,
                                    u32 hw_off, int str){
  int tq=lane&3, odd=lane&1;
  const float* bs = (const float*)(sm+BIAS) + set*512 + p*128 + wn*32;
  const float* ow = (const float*)(sm+OUTW);
  float y0=0.f, y1=0.f;
#pragma unroll
  for(int nt=0;nt<4;++nt){
    float s0 = odd? acc[nt][0]:acc[nt][2];
    float s1 = odd? acc[nt][1]:acc[nt][3];
    float r0 = __shfl_xor_sync(0xffffffffu, s0, 1);
    float r1 = __shfl_xor_sync(0xffffffffu, s1, 1);
    float gi = odd? r0 : acc[nt][0];
    float gf = odd? r1 : acc[nt][1];
    float gg = odd? acc[nt][2] : r0;
    float go = odd? acc[nt][3] : r1;
    float4 bv = *(const float4*)(bs + nt*8 + (tq>>1)*4);
    gi+=bv.x; gf+=bv.y; gg+=bv.z; go+=bv.w;
    float c = sigm(gf)*cb[nt] + sigm(gi)*tanh_(gg);
    cb[nt]=c;
    float h = sigm(go)*tanh_(c);
    __half hh=__float2half_rn(h);
    int j = p*32 + wn*8 + nt*2 + (tq>>1);
    *(u16*)(sm + hw_off + (u32)(s*str + j)*2u) = *(u16*)&hh;
    if(proj){ y0 += h*ow[j]; y1 += h*ow[128+j]; }
  }
  if(proj){ float* ps=(float*)(sm+PSUM); atomicAdd(ps+s*2,y0); atomicAdd(ps+s*2+1,y1); }
}

__global__ void __launch_bounds__(544,1)
lstm_hmma_kernel(const float* __restrict__ history, const float* __restrict__ start_token,
                 const float* __restrict__ eb0, const float* __restrict__ eb1,
                 const float* __restrict__ db0, const float* __restrict__ db1,
                 const float* __restrict__ outWg, const float* __restrict__ outb,
                 float* __restrict__ out){
  extern __shared__ char sm[];
  const u32 smb = smem_u32(sm);
  const int tid=threadIdx.x, lane=tid&31, wid=tid>>5;
  const int b0 = blockIdx.x*64;

  // ---- init ----
  for(u32 i=tid;i<BBUF/4u;i+=544) ((u32*)sm)[i]=0u;
  for(int i=tid;i<2048;i+=544){
    int st_=i>>9, n=i&511, j=n>>2, gt=n&3;
    const float* bp = st_==0?eb0: st_==1?eb1: st_==2?db0: db1;
    ((float*)(sm+BIAS))[i] = bp[gt*128+j];
  }
  for(int i=tid;i<256;i+=544) ((float*)(sm+OUTW))[i]=outWg[i];
  for(int i=tid;i<128;i+=544) ((float*)(sm+PSUM))[i]=0.f;
  if(tid<64){  // x(0) into read-buffer 0 of h0 (hi only)
    const float* hp = history + (((size_t)(b0+tid)*8)*50)*6;
#pragma unroll
    for(int f=0;f<6;++f){
      __half hh=__float2half_rn(hp[f]);
      *(u16*)(sm + H0OFF + (u32)(tid*152+128+f)*2u) = *(u16*)&hh;
    }
  }
  if(tid==0){
#pragma unroll
    for(int b=0;b<4;++b){ mbar_init(smb+MBAR+b*8, 32); mbar_init(smb+MBAR+32+b*8, 16); }
  }
  __syncthreads();

  if(wid==16){
    // ================= PRODUCER =================
    int i=0;
    for(int t=0;t<110;++t){
      const int pb=(t>=50)?26:0;
      for(int s=0;s<26;++s,++i){
        int b=i&3, r=i>>2;
        if(r>0) mbar_wait(smb+MBAR+32u+(u32)b*8u, (u32)((r&1)^1));
        const char* src=(const char*)g_B + (size_t)(pb+s)*16384 + (size_t)lane*16;
        u32 dst=smb+BBUF+(u32)b*16384u+(u32)lane*16u;
#pragma unroll
        for(int c=0;c<32;++c)
          asm volatile("cp.async.cg.shared.global [%0], [%1], 16;"
            ::"r"(dst+(u32)c*512u),"l"(src+(size_t)c*512):"memory");
        asm volatile("cp.async.mbarrier.arrive.noinc.shared.b64 [%0];"
          ::"r"(smb+MBAR+(u32)b*8u):"memory");
      }
    }
    return;
  }

  // ================= CONSUMERS (16 warps) =================
  const int wm=wid>>2, wn=wid&3, tq=lane&3;
  const int s = wm*16 + (lane>>2) + (lane&1)*8;
  const int lr=lane&7, seg=lane>>3;
  const int rowb = wm*16 + lr + (seg&1)*8;
  const int kpart = (seg>>1)*8;
  const u32 aoff152 = (u32)(rowb*152 + kpart)*2u;
  const u32 aoff136 = (u32)(rowb*136 + kpart)*2u;
  const u32 boff = (u32)(wn*128 + lane)*8u;

  float c0[16], c1[16];
#pragma unroll
  for(int i=0;i<16;++i){ c0[i]=0.f; c1[i]=0.f; }
  int i=0;
  const float st0=start_token[0], st1=start_token[1];

  for(int t=0;t<110;++t){
    const int ph=(t>=50), rw=t&1;
    const u32 h0r = H0OFF + (u32)rw*H0SZ, h0w = H0OFF + (u32)(rw^1)*H0SZ;
    const u32 h1r = H1OFF + (u32)rw*H1SZ, h1w = H1OFF + (u32)(rw^1)*H1SZ;
    // ---- layer 0: 10 slots (5 per p-pair; slot 4 = x + zero pad) ----
#pragma unroll
    for(int pp=0;pp<2;++pp){
      float A2[2][4][4];
#pragma unroll
      for(int u=0;u<2;++u)
#pragma unroll
        for(int a=0;a<4;++a){A2[u][a][0]=0;A2[u][a][1]=0;A2[u][a][2]=0;A2[u][a][3]=0;}
#pragma unroll 1
      for(int sl=0;sl<5;++sl)
        cslot2(sm,smb,i,boff, h0r, aoff152, 2*sl, lane, A2);
      epi(sm, A2[0], c0+(2*pp+0)*4, ph*2+0, 2*pp+0, wn, lane, s, false, h0w, 152);
      epi(sm, A2[1], c0+(2*pp+1)*4, ph*2+0, 2*pp+1, wn, lane, s, false, h0w, 152);
    }
    BARC();
    // ---- layer 1: 16 slots (8 per p-pair) ----
#pragma unroll
    for(int pp=0;pp<2;++pp){
      float A2[2][4][4];
#pragma unroll
      for(int u=0;u<2;++u)
#pragma unroll
        for(int a=0;a<4;++a){A2[u][a][0]=0;A2[u][a][1]=0;A2[u][a][2]=0;A2[u][a][3]=0;}
#pragma unroll 1
      for(int pr=0;pr<8;++pr){
        if(pr<4) cslot2(sm,smb,i,boff, h0w, aoff152, 2*pr,   lane, A2);
        else     cslot2(sm,smb,i,boff, h1r, aoff136, 2*pr-8, lane, A2);
      }
      epi(sm, A2[0], c1+(2*pp+0)*4, ph*2+1, 2*pp+0, wn, lane, s, ph!=0, h1w, 136);
      epi(sm, A2[1], c1+(2*pp+1)*4, ph*2+1, 2*pp+1, wn, lane, s, ph!=0, h1w, 136);
    }
    // ---- tail ----
    if(!ph){
      if(tid<64){
        float xv[6];
        if(t+1<50){
          const float* hp = history + (((size_t)(b0+tid)*8)*50 + (size_t)(t+1))*6;
#pragma unroll
          for(int f=0;f<6;++f) xv[f]=hp[f];
        } else { xv[0]=st0; xv[1]=st1; xv[2]=0; xv[3]=0; xv[4]=0; xv[5]=0; }
#pragma unroll
        for(int f=0;f<6;++f){
          __half hh=__float2half_rn(xv[f]);
          *(u16*)(sm + h0w + (u32)(tid*152+128+f)*2u) = *(u16*)&hh;
        }
      }
      BARC();
    } else {
      BARC();
      if(tid<128){
        int ss=tid>>1, o=tid&1;
        float y = ((float*)(sm+PSUM))[tid] + outb[o];
        out[((size_t)(b0+ss)*60 + (size_t)(t-50))*2 + o] = y;
        ((float*)(sm+PSUM))[tid]=0.f;
        __half hh=__float2half_rn(y);
        *(u16*)(sm + h0w + (u32)(ss*152+128+o)*2u) = *(u16*)&hh;
      }
      BARC();
    }
  }
}

extern "C" void kernel_launch(void* const* d_in, const int* in_sizes, int n_in,
                              void* d_out, int out_size){
  const float* history     = (const float*)d_in[0];
  const float* start_token = (const float*)d_in[1];
  const float* eWih0=(const float*)d_in[2],  *eWhh0=(const float*)d_in[3],  *eb0=(const float*)d_in[4];
  const float* eWih1=(const float*)d_in[5],  *eWhh1=(const float*)d_in[6],  *eb1=(const float*)d_in[7];
  const float* dWih0=(const float*)d_in[8],  *dWhh0=(const float*)d_in[9],  *db0=(const float*)d_in[10];
  const float* dWih1=(const float*)d_in[11], *dWhh1=(const float*)d_in[12], *db1=(const float*)d_in[13];
  const float* outW=(const float*)d_in[14],  *outb=(const float*)d_in[15];
  float* out=(float*)d_out;
  (void)in_sizes; (void)n_in; (void)out_size;

  cudaFuncSetAttribute(lstm_hmma_kernel, cudaFuncAttributeMaxDynamicSharedMemorySize, SMSZ);

  prep_kernel<<<208, 256>>>(eWih0,eWhh0,eWih1,eWhh1,dWih0,dWhh0,dWih1,dWhh1);
  lstm_hmma_kernel<<<256, 544, SMSZ>>>(history,start_token,eb0,eb1,db0,db1,outW,outb,out);
}

// round 16
// speedup vs baseline: 6.0106x; 1.1014x over previous
#include <cuda_runtime.h>
#include <cuda_fp16.h>
#include <cstdint>
#include <cstddef>

typedef unsigned int u32; typedef unsigned short u16;

// ---- smem layout (bytes) ---- (identical to R13)
#define H0OFF  0u
#define H0SZ   19456u      // 64 x 152 halfs (x in cols 128..133), 2 buffers
#define H1OFF  77824u
#define H1SZ   17408u      // 64 x 136 halfs, 2 buffers
#define BBUF   147456u     // 4 x 16384 slot ring
#define BIAS   212992u
#define OUTW   221184u
#define PSUM   222208u
#define MBAR   222720u     // full[4]@+0, empty[4]@+32
#define SMSZ   222784u

// weight stream: per phase 26 slots x 16KB; slot = 4 x 4KB sub-units:
//   [kkA p_even][kkA p_odd][kkB p_even][kkB p_odd]
// sub-unit (nt-PAIRED): [ntpair 0..7][lane 0..31][16B = b0,b1(nt even), b0,b1(nt odd)]
__device__ uint4 g_B[2 * 26 * 1024];

__device__ __forceinline__ u32 smem_u32(const void* p){
  u32 a; asm("{ .reg .u64 t; cvta.to.shared.u64 t, %1; cvt.u32.u64 %0, t; }":"=r"(a):"l"(p)); return a;
}
__device__ __forceinline__ float sigm(float v){
  return __fdividef(1.0f, 1.0f+__expf(-v));
}
__device__ __forceinline__ float tanh_(float v){
  float ax=fabsf(v), e=__expf(-2.0f*ax);
  return copysignf(__fdividef(1.0f-e,1.0f+e), v);
}
#define MMA(d,a0,a1,a2,a3,b0,b1) \
  asm volatile("mma.sync.aligned.m16n8k16.row.col.f32.f16.f16.f32 " \
    "{%0,%1,%2,%3},{%4,%5,%6,%7},{%8,%9},{%0,%1,%2,%3};" \
    :"+f"(d[0]),"+f"(d[1]),"+f"(d[2]),"+f"(d[3]) \
    :"r"(a0),"r"(a1),"r"(a2),"r"(a3),"r"(b0),"r"(b1))

__device__ __forceinline__ void mbar_init(u32 mb,u32 c){
  asm volatile("mbarrier.init.shared.b64 [%0], %1;"::"r"(mb),"r"(c):"memory");
}
__device__ __forceinline__ void mbar_wait(u32 mb,u32 ph){
  u32 done;
  asm volatile("{\n\t.reg .pred p;\n\t"
    "mbarrier.try_wait.parity.acquire.cta.shared::cta.b64 p, [%1], %2;\n\t"
    "selp.b32 %0, 1, 0, p;\n\t}":"=r"(done):"r"(mb),"r"(ph):"memory");
  if(!done){
    asm volatile("{\n\t.reg .pred P1;\n\tWL_%=:\n\t"
      "mbarrier.try_wait.parity.acquire.cta.shared::cta.b64 P1, [%0], %1, 0x989680;\n\t"
      "@P1 bra.uni WD_%=;\n\tbra.uni WL_%=;\n\tWD_%=:\n\t}"::"r"(mb),"r"(ph):"memory");
  }
}
#define BARC() asm volatile("bar.sync 1, 512;":::"memory")

// ===== prep: 208 blocks = 2 ph x 26 slots x 4 sub-units; nt-paired 16B groups =====
__global__ void prep_kernel(const float* eWih0,const float* eWhh0,const float* eWih1,const float* eWhh1,
                            const float* dWih0,const float* dWhh0,const float* dWih1,const float* dWhh1){
  int gu=blockIdx.x, ph=gu/104, r=gu%104, s=r/4, m=r%4;
  int kk=m>>1, half=m&1;
  const float* Wx = ph? dWih0 : eWih0; int nf = ph?2:6;
  const float* M=nullptr; int p, kb=0, isx=0, isz=0;
  if(s<10){
    int pp=s/5, sl=s%5; p=pp*2+half;
    if(sl<4){ M = ph?dWhh0:eWhh0; kb = 2*sl+kk; }
    else { if(kk==0) isx=1; else isz=1; }
  } else {
    int v=s-10, pp=v/8, pr=v%8; p=pp*2+half;
    int kq=2*pr+kk;
    if(kq<8){ M=ph?dWih1:eWih1; kb=kq; } else { M=ph?dWhh1:eWhh1; kb=kq-8; }
  }
  u32* dst=(u32*)g_B + (((size_t)(ph*26+s))*4 + (size_t)m)*1024;
  for(int e=threadIdx.x;e<1024;e+=256){
    // e = ntp*128 + lane*4 + w ; w: 0=b0(nt=2ntp) 1=b1(2ntp) 2=b0(2ntp+1) 3=b1(2ntp+1)
    int ntp=e>>7, lane=(e>>2)&31, w=e&3;
    int nt=2*ntp+(w>>1), q=w&1;
    int g=lane>>2, tq=lane&3;
    int n_loc=nt*8+g, k_loc=tq*2+q*8;
    int ng=p*128+n_loc, j=ng>>2, gt=ng&3, wr=gt*128+j;
    float w0=0.f, w1=0.f;
    if(isz){ /* zero pad */ }
    else if(isx){
      if(k_loc<nf)   w0=Wx[wr*nf+k_loc];
      if(k_loc+1<nf) w1=Wx[wr*nf+k_loc+1];
    } else {
      w0=M[wr*128+kb*16+k_loc]; w1=M[wr*128+kb*16+k_loc+1];
    }
    __half h0=__float2half_rn(w0), h1=__float2half_rn(w1);
    dst[e] = (u32)(*(u16*)&h0) | ((u32)(*(u16*)&h1)<<16);
  }
}

// ===== consumer: one 16KB slot = 2 kb x (warp's half+ntq); 16 MMA, B reused over mt =====
__device__ __forceinline__ void cslot2(char* sm,u32 smb,int& i,u32 buntq,
                                       u32 hab,const u32* aof,int akb0,int lane,
                                       float (&acc)[2][4][4]){
  int b=i&3, r=i>>2; ++i;
  mbar_wait(smb+MBAR+(u32)b*8u, (u32)(r&1));
  u32 bslot = BBUF + (u32)b*16384u + buntq;
#pragma unroll
  for(int kk=0;kk<2;++kk){
    u32 a0[4], a1[4];
    u32 ad0 = hab + aof[0] + (u32)(akb0+kk)*32u;
    u32 ad1 = hab + aof[1] + (u32)(akb0+kk)*32u;
    asm volatile("ldmatrix.sync.aligned.m8n8.x4.shared.b16 {%0,%1,%2,%3},[%4];"
      :"=r"(a0[0]),"=r"(a0[1]),"=r"(a0[2]),"=r"(a0[3]):"r"(ad0));
    asm volatile("ldmatrix.sync.aligned.m8n8.x4.shared.b16 {%0,%1,%2,%3},[%4];"
      :"=r"(a1[0]),"=r"(a1[1]),"=r"(a1[2]),"=r"(a1[3]):"r"(ad1));
    u32 bb = bslot + (u32)kk*8192u;
    uint4 bv0 = *(uint4*)(sm + bb);
    uint4 bv1 = *(uint4*)(sm + bb + 512u);
    MMA(acc[0][0], a0[0],a0[1],a0[2],a0[3], bv0.x,bv0.y);
    MMA(acc[0][1], a0[0],a0[1],a0[2],a0[3], bv0.z,bv0.w);
    MMA(acc[0][2], a0[0],a0[1],a0[2],a0[3], bv1.x,bv1.y);
    MMA(acc[0][3], a0[0],a0[1],a0[2],a0[3], bv1.z,bv1.w);
    MMA(acc[1][0], a1[0],a1[1],a1[2],a1[3], bv0.x,bv0.y);
    MMA(acc[1][1], a1[0],a1[1],a1[2],a1[3], bv0.z,bv0.w);
    MMA(acc[1][2], a1[0],a1[1],a1[2],a1[3], bv1.x,bv1.y);
    MMA(acc[1][3], a1[0],a1[1],a1[2],a1[3], bv1.z,bv1.w);
  }
  __syncwarp();
  if(lane==0)
    asm volatile("mbarrier.arrive.shared.b64 _, [%0];"::"r"(smb+MBAR+32u+(u32)b*8u):"memory");
}

// ===== epilogue for one pp (2 mt x 4 nt cells), p = pp*2+uu =====
__device__ __forceinline__ void epi(char* sm, float (&acc)[2][4][4], float* cb,
                                    int set, int p, int ntq, int wm, int lane, bool proj,
                                    u32 hw_off, int str){
  int tq=lane&3, odd=lane&1;
  const float* bs = (const float*)(sm+BIAS) + set*512 + p*128 + ntq*32;
  const float* ow = (const float*)(sm+OUTW);
#pragma unroll
  for(int mt=0;mt<2;++mt){
    int s = wm*32 + mt*16 + (lane>>2) + (lane&1)*8;
    float y0=0.f, y1=0.f;
#pragma unroll
    for(int nt=0;nt<4;++nt){
      float s0 = odd? acc[mt][nt][0]:acc[mt][nt][2];
      float s1 = odd? acc[mt][nt][1]:acc[mt][nt][3];
      float r0 = __shfl_xor_sync(0xffffffffu, s0, 1);
      float r1 = __shfl_xor_sync(0xffffffffu, s1, 1);
      float gi = odd? r0 : acc[mt][nt][0];
      float gf = odd? r1 : acc[mt][nt][1];
      float gg = odd? acc[mt][nt][2] : r0;
      float go = odd? acc[mt][nt][3] : r1;
      float4 bv = *(const float4*)(bs + nt*8 + (tq>>1)*4);
      gi+=bv.x; gf+=bv.y; gg+=bv.z; go+=bv.w;
      float c = sigm(gf)*cb[mt*4+nt] + sigm(gi)*tanh_(gg);
      cb[mt*4+nt]=c;
      float h = sigm(go)*tanh_(c);
      __half hh=__float2half_rn(h);
      int j = p*32 + ntq*8 + nt*2 + (tq>>1);
      *(u16*)(sm + hw_off + (u32)(s*str + j)*2u) = *(u16*)&hh;
      if(proj){ y0 += h*ow[j]; y1 += h*ow[128+j]; }
    }
    if(proj){ float* ps=(float*)(sm+PSUM); atomicAdd(ps+s*2,y0); atomicAdd(ps+s*2+1,y1); }
  }
}

__global__ void __launch_bounds__(544,1)
lstm_hmma_kernel(const float* __restrict__ history, const float* __restrict__ start_token,
                 const float* __restrict__ eb0, const float* __restrict__ eb1,
                 const float* __restrict__ db0, const float* __restrict__ db1,
                 const float* __restrict__ outWg, const float* __restrict__ outb,
                 float* __restrict__ out){
  extern __shared__ char sm[];
  const u32 smb = smem_u32(sm);
  const int tid=threadIdx.x, lane=tid&31, wid=tid>>5;
  const int b0 = blockIdx.x*64;

  // ---- init ----
  for(u32 i=tid;i<BBUF/4u;i+=544) ((u32*)sm)[i]=0u;   // h tiles zero
  for(int i=tid;i<2048;i+=544){
    int st_=i>>9, n=i&511, j=n>>2, gt=n&3;
    const float* bp = st_==0?eb0: st_==1?eb1: st_==2?db0: db1;
    ((float*)(sm+BIAS))[i] = bp[gt*128+j];
  }
  for(int i=tid;i<256;i+=544) ((float*)(sm+OUTW))[i]=outWg[i];
  for(int i=tid;i<128;i+=544) ((float*)(sm+PSUM))[i]=0.f;
  if(tid<64){  // x(0) into read-buffer 0 of h0 (hi only)
    const float* hp = history + (((size_t)(b0+tid)*8)*50)*6;
#pragma unroll
    for(int f=0;f<6;++f){
      __half hh=__float2half_rn(hp[f]);
      *(u16*)(sm + H0OFF + (u32)(tid*152+128+f)*2u) = *(u16*)&hh;
    }
  }
  if(tid==0){
#pragma unroll
    for(int b=0;b<4;++b){ mbar_init(smb+MBAR+b*8, 32); mbar_init(smb+MBAR+32+b*8, 16); }
  }
  __syncthreads();

  if(wid==16){
    // ================= PRODUCER (identical to R13: 26 slots x 16KB / step) ======
    int i=0;
    for(int t=0;t<110;++t){
      const int pb=(t>=50)?26:0;
      for(int s=0;s<26;++s,++i){
        int b=i&3, r=i>>2;
        if(r>0) mbar_wait(smb+MBAR+32u+(u32)b*8u, (u32)((r&1)^1));
        const char* src=(const char*)g_B + (size_t)(pb+s)*16384 + (size_t)lane*16;
        u32 dst=smb+BBUF+(u32)b*16384u+(u32)lane*16u;
#pragma unroll
        for(int c=0;c<32;++c)
          asm volatile("cp.async.cg.shared.global [%0], [%1], 16;"
            ::"r"(dst+(u32)c*512u),"l"(src+(size_t)c*512):"memory");
        asm volatile("cp.async.mbarrier.arrive.noinc.shared.b64 [%0];"
          ::"r"(smb+MBAR+(u32)b*8u):"memory");
      }
    }
    return;
  }

  // ================= CONSUMERS (16 warps: wm 0..1, uu 0..1, ntq 0..3) =========
  const int wm=wid>>3, wn=wid&7, uu=wn>>2, ntq=wn&3;
  const int lr=lane&7, seg=lane>>3;
  const int kpart = (seg>>1)*8;
  u32 aoff152[2], aoff136[2];
#pragma unroll
  for(int mt=0;mt<2;++mt){
    int rowb = wm*32 + mt*16 + lr + (seg&1)*8;
    aoff152[mt] = (u32)(rowb*152 + kpart)*2u;
    aoff136[mt] = (u32)(rowb*136 + kpart)*2u;
  }
  const u32 buntq = (u32)uu*4096u + (u32)ntq*1024u + (u32)lane*16u;

  float c0[16], c1[16];
#pragma unroll
  for(int i=0;i<16;++i){ c0[i]=0.f; c1[i]=0.f; }
  int i=0;
  const float st0=start_token[0], st1=start_token[1];

  for(int t=0;t<110;++t){
    const int ph=(t>=50), rw=t&1;
    const u32 h0r = H0OFF + (u32)rw*H0SZ, h0w = H0OFF + (u32)(rw^1)*H0SZ;
    const u32 h1r = H1OFF + (u32)rw*H1SZ, h1w = H1OFF + (u32)(rw^1)*H1SZ;
    // ---- layer 0: 10 slots (5 per pp; slot 4 = x + zero pad) ----
#pragma unroll
    for(int pp=0;pp<2;++pp){
      float acc[2][4][4];
#pragma unroll
      for(int mt=0;mt<2;++mt)
#pragma unroll
        for(int a=0;a<4;++a){acc[mt][a][0]=0;acc[mt][a][1]=0;acc[mt][a][2]=0;acc[mt][a][3]=0;}
#pragma unroll 1
      for(int sl=0;sl<5;++sl)
        cslot2(sm,smb,i,buntq, smb+h0r, aoff152, 2*sl, lane, acc);
      epi(sm, acc, (pp? c0+8 : c0), ph*2+0, pp*2+uu, ntq, wm, lane, false, h0w, 152);
    }
    BARC();
    // ---- layer 1: 16 slots (8 per pp) ----
#pragma unroll
    for(int pp=0;pp<2;++pp){
      float acc[2][4][4];
#pragma unroll
      for(int mt=0;mt<2;++mt)
#pragma unroll
        for(int a=0;a<4;++a){acc[mt][a][0]=0;acc[mt][a][1]=0;acc[mt][a][2]=0;acc[mt][a][3]=0;}
#pragma unroll 1
      for(int pr=0;pr<8;++pr){
        if(pr<4) cslot2(sm,smb,i,buntq, smb+h0w, aoff152, 2*pr,   lane, acc);
        else     cslot2(sm,smb,i,buntq, smb+h1r, aoff136, 2*pr-8, lane, acc);
      }
      epi(sm, acc, (pp? c1+8 : c1), ph*2+1, pp*2+uu, ntq, wm, lane, ph!=0, h1w, 136);
    }
    // ---- tail ----
    if(!ph){
      if(tid<64){
        float xv[6];
        if(t+1<50){
          const float* hp = history + (((size_t)(b0+tid)*8)*50 + (size_t)(t+1))*6;
#pragma unroll
          for(int f=0;f<6;++f) xv[f]=hp[f];
        } else { xv[0]=st0; xv[1]=st1; xv[2]=0; xv[3]=0; xv[4]=0; xv[5]=0; }
#pragma unroll
        for(int f=0;f<6;++f){
          __half hh=__float2half_rn(xv[f]);
          *(u16*)(sm + h0w + (u32)(tid*152+128+f)*2u) = *(u16*)&hh;
        }
      }
      BARC();
    } else {
      BARC();
      if(tid<128){
        int ss=tid>>1, o=tid&1;
        float y = ((float*)(sm+PSUM))[tid] + outb[o];
        out[((size_t)(b0+ss)*60 + (size_t)(t-50))*2 + o] = y;
        ((float*)(sm+PSUM))[tid]=0.f;
        __half hh=__float2half_rn(y);
        *(u16*)(sm + h0w + (u32)(ss*152+128+o)*2u) = *(u16*)&hh;
      }
      BARC();
    }
  }
}

extern "C" void kernel_launch(void* const* d_in, const int* in_sizes, int n_in,
                              void* d_out, int out_size){
  const float* history     = (const float*)d_in[0];
  const float* start_token = (const float*)d_in[1];
  const float* eWih0=(const float*)d_in[2],  *eWhh0=(const float*)d_in[3],  *eb0=(const float*)d_in[4];
  const float* eWih1=(const float*)d_in[5],  *eWhh1=(const float*)d_in[6],  *eb1=(const float*)d_in[7];
  const float* dWih0=(const float*)d_in[8],  *dWhh0=(const float*)d_in[9],  *db0=(const float*)d_in[10];
  const float* dWih1=(const float*)d_in[11], *dWhh1=(const float*)d_in[12], *db1=(const float*)d_in[13];
  const float* outW=(const float*)d_in[14],  *outb=(const float*)d_in[15];
  float* out=(float*)d_out;
  (void)in_sizes; (void)n_in; (void)out_size;

  cudaFuncSetAttribute(lstm_hmma_kernel, cudaFuncAttributeMaxDynamicSharedMemorySize, SMSZ);

  prep_kernel<<<208, 256>>>(eWih0,eWhh0,eWih1,eWhh1,dWih0,dWhh0,dWih1,dWhh1);
  lstm_hmma_kernel<<<256, 544, SMSZ>>>(history,start_token,eb0,eb1,db0,db1,outW,outb,out);
}

// round 17
// speedup vs baseline: 7.2364x; 1.2039x over previous
#include <cuda_runtime.h>
#include <cuda_fp16.h>
#include <cstdint>
#include <cstddef>

typedef unsigned int u32; typedef unsigned short u16;

// ---- smem layout (bytes) ---- (identical to R15)
#define H0OFF  0u
#define H0SZ   19456u      // 64 x 152 halfs (x in cols 128..133), 2 buffers
#define H1OFF  77824u
#define H1SZ   17408u      // 64 x 136 halfs, 2 buffers
#define BBUF   147456u     // 4 x 16384 slot ring
#define BIAS   212992u
#define OUTW   221184u
#define PSUM   222208u
#define MBAR   222720u     // full[4]@+0, empty[4]@+32
#define SMSZ   222784u

// weight stream: per phase 26 slots x 16KB; slot = 4 x 4KB sub-units:
//   [kkA p_even][kkA p_odd][kkB p_even][kkB p_odd]
// sub-unit (nt-PAIRED): [ntpair 0..7][lane 0..31][16B = b0,b1(nt even), b0,b1(nt odd)]
__device__ uint4 g_B[2 * 26 * 1024];

__device__ __forceinline__ u32 smem_u32(const void* p){
  u32 a; asm("{ .reg .u64 t; cvta.to.shared.u64 t, %1; cvt.u32.u64 %0, t; }":"=r"(a):"l"(p)); return a;
}
// ---- hardware tanh activations ----
__device__ __forceinline__ float tanh_(float v){
  float r; asm("tanh.approx.f32 %0, %1;":"=f"(r):"f"(v)); return r;
}
__device__ __forceinline__ float sigm(float v){
  float r; asm("tanh.approx.f32 %0, %1;":"=f"(r):"f"(0.5f*v));
  return fmaf(0.5f, r, 0.5f);
}
#define MMA(d,a0,a1,a2,a3,b0,b1) \
  asm volatile("mma.sync.aligned.m16n8k16.row.col.f32.f16.f16.f32 " \
    "{%0,%1,%2,%3},{%4,%5,%6,%7},{%8,%9},{%0,%1,%2,%3};" \
    :"+f"(d[0]),"+f"(d[1]),"+f"(d[2]),"+f"(d[3]) \
    :"r"(a0),"r"(a1),"r"(a2),"r"(a3),"r"(b0),"r"(b1))

__device__ __forceinline__ void mbar_init(u32 mb,u32 c){
  asm volatile("mbarrier.init.shared.b64 [%0], %1;"::"r"(mb),"r"(c):"memory");
}
__device__ __forceinline__ void mbar_wait(u32 mb,u32 ph){
  u32 done;
  asm volatile("{\n\t.reg .pred p;\n\t"
    "mbarrier.try_wait.parity.acquire.cta.shared::cta.b64 p, [%1], %2;\n\t"
    "selp.b32 %0, 1, 0, p;\n\t}":"=r"(done):"r"(mb),"r"(ph):"memory");
  if(!done){
    asm volatile("{\n\t.reg .pred P1;\n\tWL_%=:\n\t"
      "mbarrier.try_wait.parity.acquire.cta.shared::cta.b64 P1, [%0], %1, 0x989680;\n\t"
      "@P1 bra.uni WD_%=;\n\tbra.uni WL_%=;\n\tWD_%=:\n\t}"::"r"(mb),"r"(ph):"memory");
  }
}
#define BARC() asm volatile("bar.sync 1, 512;":::"memory")

// ===== prep: 208 blocks = 2 ph x 26 slots x 4 sub-units; nt-paired 16B groups =====
__global__ void prep_kernel(const float* eWih0,const float* eWhh0,const float* eWih1,const float* eWhh1,
                            const float* dWih0,const float* dWhh0,const float* dWih1,const float* dWhh1){
  int gu=blockIdx.x, ph=gu/104, r=gu%104, s=r/4, m=r%4;
  int kk=m>>1, half=m&1;
  const float* Wx = ph? dWih0 : eWih0; int nf = ph?2:6;
  const float* M=nullptr; int p, kb=0, isx=0, isz=0;
  if(s<10){
    int pp=s/5, sl=s%5; p=pp*2+half;
    if(sl<4){ M = ph?dWhh0:eWhh0; kb = 2*sl+kk; }
    else { if(kk==0) isx=1; else isz=1; }
  } else {
    int v=s-10, pp=v/8, pr=v%8; p=pp*2+half;
    int kq=2*pr+kk;
    if(kq<8){ M=ph?dWih1:eWih1; kb=kq; } else { M=ph?dWhh1:eWhh1; kb=kq-8; }
  }
  u32* dst=(u32*)g_B + (((size_t)(ph*26+s))*4 + (size_t)m)*1024;
  for(int e=threadIdx.x;e<1024;e+=256){
    int ntp=e>>7, lane=(e>>2)&31, w=e&3;
    int nt=2*ntp+(w>>1), q=w&1;
    int g=lane>>2, tq=lane&3;
    int n_loc=nt*8+g, k_loc=tq*2+q*8;
    int ng=p*128+n_loc, j=ng>>2, gt=ng&3, wr=gt*128+j;
    float w0=0.f, w1=0.f;
    if(isz){ /* zero pad */ }
    else if(isx){
      if(k_loc<nf)   w0=Wx[wr*nf+k_loc];
      if(k_loc+1<nf) w1=Wx[wr*nf+k_loc+1];
    } else {
      w0=M[wr*128+kb*16+k_loc]; w1=M[wr*128+kb*16+k_loc+1];
    }
    __half h0=__float2half_rn(w0), h1=__float2half_rn(w1);
    dst[e] = (u32)(*(u16*)&h0) | ((u32)(*(u16*)&h1)<<16);
  }
}

// ===== consumer: one 16KB slot; 16 MMA, B reused over mt =====
__device__ __forceinline__ void cslot2(char* sm,u32 smb,int& i,u32 buntq,
                                       u32 hab,const u32* aof,int akb0,int lane,
                                       float (&acc)[2][4][4]){
  int b=i&3, r=i>>2; ++i;
  mbar_wait(smb+MBAR+(u32)b*8u, (u32)(r&1));
  u32 bslot = BBUF + (u32)b*16384u + buntq;
#pragma unroll
  for(int kk=0;kk<2;++kk){
    u32 a0[4], a1[4];
    u32 ad0 = hab + aof[0] + (u32)(akb0+kk)*32u;
    u32 ad1 = hab + aof[1] + (u32)(akb0+kk)*32u;
    asm volatile("ldmatrix.sync.aligned.m8n8.x4.shared.b16 {%0,%1,%2,%3},[%4];"
      :"=r"(a0[0]),"=r"(a0[1]),"=r"(a0[2]),"=r"(a0[3]):"r"(ad0));
    asm volatile("ldmatrix.sync.aligned.m8n8.x4.shared.b16 {%0,%1,%2,%3},[%4];"
      :"=r"(a1[0]),"=r"(a1[1]),"=r"(a1[2]),"=r"(a1[3]):"r"(ad1));
    u32 bb = bslot + (u32)kk*8192u;
    uint4 bv0 = *(uint4*)(sm + bb);
    uint4 bv1 = *(uint4*)(sm + bb + 512u);
    MMA(acc[0][0], a0[0],a0[1],a0[2],a0[3], bv0.x,bv0.y);
    MMA(acc[0][1], a0[0],a0[1],a0[2],a0[3], bv0.z,bv0.w);
    MMA(acc[0][2], a0[0],a0[1],a0[2],a0[3], bv1.x,bv1.y);
    MMA(acc[0][3], a0[0],a0[1],a0[2],a0[3], bv1.z,bv1.w);
    MMA(acc[1][0], a1[0],a1[1],a1[2],a1[3], bv0.x,bv0.y);
    MMA(acc[1][1], a1[0],a1[1],a1[2],a1[3], bv0.z,bv0.w);
    MMA(acc[1][2], a1[0],a1[1],a1[2],a1[3], bv1.x,bv1.y);
    MMA(acc[1][3], a1[0],a1[1],a1[2],a1[3], bv1.z,bv1.w);
  }
  __syncwarp();
  if(lane==0)
    asm volatile("mbarrier.arrive.shared.b64 _, [%0];"::"r"(smb+MBAR+32u+(u32)b*8u):"memory");
}

// ===== epilogue for one pp (2 mt x 4 nt cells), p = pp*2+uu =====
__device__ __forceinline__ void epi(char* sm, float (&acc)[2][4][4], float* cb,
                                    int set, int p, int ntq, int wm, int lane, bool proj,
                                    u32 hw_off, int str){
  int tq=lane&3, odd=lane&1;
  const float* bs = (const float*)(sm+BIAS) + set*512 + p*128 + ntq*32;
  const float* ow = (const float*)(sm+OUTW);
#pragma unroll
  for(int mt=0;mt<2;++mt){
    int s = wm*32 + mt*16 + (lane>>2) + (lane&1)*8;
    float y0=0.f, y1=0.f;
#pragma unroll
    for(int nt=0;nt<4;++nt){
      float s0 = odd? acc[mt][nt][0]:acc[mt][nt][2];
      float s1 = odd? acc[mt][nt][1]:acc[mt][nt][3];
      float r0 = __shfl_xor_sync(0xffffffffu, s0, 1);
      float r1 = __shfl_xor_sync(0xffffffffu, s1, 1);
      float gi = odd? r0 : acc[mt][nt][0];
      float gf = odd? r1 : acc[mt][nt][1];
      float gg = odd? acc[mt][nt][2] : r0;
      float go = odd? acc[mt][nt][3] : r1;
      float4 bv = *(const float4*)(bs + nt*8 + (tq>>1)*4);
      gi+=bv.x; gf+=bv.y; gg+=bv.z; go+=bv.w;
      float c = sigm(gf)*cb[mt*4+nt] + sigm(gi)*tanh_(gg);
      cb[mt*4+nt]=c;
      float h = sigm(go)*tanh_(c);
      __half hh=__float2half_rn(h);
      int j = p*32 + ntq*8 + nt*2 + (tq>>1);
      *(u16*)(sm + hw_off + (u32)(s*str + j)*2u) = *(u16*)&hh;
      if(proj){ y0 += h*ow[j]; y1 += h*ow[128+j]; }
    }
    if(proj){ float* ps=(float*)(sm+PSUM); atomicAdd(ps+s*2,y0); atomicAdd(ps+s*2+1,y1); }
  }
}

__global__ void __launch_bounds__(544,1)
lstm_hmma_kernel(const float* __restrict__ history, const float* __restrict__ start_token,
                 const float* __restrict__ eb0, const float* __restrict__ eb1,
                 const float* __restrict__ db0, const float* __restrict__ db1,
                 const float* __restrict__ outWg, const float* __restrict__ outb,
                 float* __restrict__ out){
  extern __shared__ char sm[];
  const u32 smb = smem_u32(sm);
  const int tid=threadIdx.x, lane=tid&31, wid=tid>>5;
  const int b0 = blockIdx.x*64;

  // ---- init ----
  for(u32 i=tid;i<BBUF/4u;i+=544) ((u32*)sm)[i]=0u;   // h tiles zero
  for(int i=tid;i<2048;i+=544){
    int st_=i>>9, n=i&511, j=n>>2, gt=n&3;
    const float* bp = st_==0?eb0: st_==1?eb1: st_==2?db0: db1;
    ((float*)(sm+BIAS))[i] = bp[gt*128+j];
  }
  for(int i=tid;i<256;i+=544) ((float*)(sm+OUTW))[i]=outWg[i];
  for(int i=tid;i<128;i+=544) ((float*)(sm+PSUM))[i]=0.f;
  if(tid<64){  // x(0) into read-buffer 0 of h0 (hi only)
    const float* hp = history + (((size_t)(b0+tid)*8)*50)*6;
#pragma unroll
    for(int f=0;f<6;++f){
      __half hh=__float2half_rn(hp[f]);
      *(u16*)(sm + H0OFF + (u32)(tid*152+128+f)*2u) = *(u16*)&hh;
    }
  }
  if(tid==0){
#pragma unroll
    for(int b=0;b<4;++b){ mbar_init(smb+MBAR+b*8, 32); mbar_init(smb+MBAR+32+b*8, 16); }
  }
  __syncthreads();

  if(wid==16){
    // ================= PRODUCER =================
    int i=0;
    for(int t=0;t<110;++t){
      const int pb=(t>=50)?26:0;
      for(int s=0;s<26;++s,++i){
        int b=i&3, r=i>>2;
        if(r>0) mbar_wait(smb+MBAR+32u+(u32)b*8u, (u32)((r&1)^1));
        const char* src=(const char*)g_B + (size_t)(pb+s)*16384 + (size_t)lane*16;
        u32 dst=smb+BBUF+(u32)b*16384u+(u32)lane*16u;
#pragma unroll
        for(int c=0;c<32;++c)
          asm volatile("cp.async.cg.shared.global [%0], [%1], 16;"
            ::"r"(dst+(u32)c*512u),"l"(src+(size_t)c*512):"memory");
        asm volatile("cp.async.mbarrier.arrive.noinc.shared.b64 [%0];"
          ::"r"(smb+MBAR+(u32)b*8u):"memory");
      }
    }
    return;
  }

  // ================= CONSUMERS (16 warps: wm 0..1, uu 0..1, ntq 0..3) =========
  const int wm=wid>>3, wn=wid&7, uu=wn>>2, ntq=wn&3;
  const int lr=lane&7, seg=lane>>3;
  const int kpart = (seg>>1)*8;
  u32 aoff152[2], aoff136[2];
#pragma unroll
  for(int mt=0;mt<2;++mt){
    int rowb = wm*32 + mt*16 + lr + (seg&1)*8;
    aoff152[mt] = (u32)(rowb*152 + kpart)*2u;
    aoff136[mt] = (u32)(rowb*136 + kpart)*2u;
  }
  const u32 buntq = (u32)uu*4096u + (u32)ntq*1024u + (u32)lane*16u;

  float c0[16], c1[16];
#pragma unroll
  for(int i=0;i<16;++i){ c0[i]=0.f; c1[i]=0.f; }
  int i=0;
  const float st0=start_token[0], st1=start_token[1];

  for(int t=0;t<110;++t){
    const int ph=(t>=50), rw=t&1;
    const u32 h0r = H0OFF + (u32)rw*H0SZ, h0w = H0OFF + (u32)(rw^1)*H0SZ;
    const u32 h1r = H1OFF + (u32)rw*H1SZ, h1w = H1OFF + (u32)(rw^1)*H1SZ;
    // ---- layer 0: 10 slots (5 per pp; slot 4 = x + zero pad) ----
#pragma unroll
    for(int pp=0;pp<2;++pp){
      float acc[2][4][4];
#pragma unroll
      for(int mt=0;mt<2;++mt)
#pragma unroll
        for(int a=0;a<4;++a){acc[mt][a][0]=0;acc[mt][a][1]=0;acc[mt][a][2]=0;acc[mt][a][3]=0;}
#pragma unroll 1
      for(int sl=0;sl<5;++sl)
        cslot2(sm,smb,i,buntq, smb+h0r, aoff152, 2*sl, lane, acc);
      epi(sm, acc, (pp? c0+8 : c0), ph*2+0, pp*2+uu, ntq, wm, lane, false, h0w, 152);
    }
    BARC();
    // ---- layer 1: 16 slots (8 per pp) ----
#pragma unroll
    for(int pp=0;pp<2;++pp){
      float acc[2][4][4];
#pragma unroll
      for(int mt=0;mt<2;++mt)
#pragma unroll
        for(int a=0;a<4;++a){acc[mt][a][0]=0;acc[mt][a][1]=0;acc[mt][a][2]=0;acc[mt][a][3]=0;}
#pragma unroll 1
      for(int pr=0;pr<8;++pr){
        if(pr<4) cslot2(sm,smb,i,buntq, smb+h0w, aoff152, 2*pr,   lane, acc);
        else     cslot2(sm,smb,i,buntq, smb+h1r, aoff136, 2*pr-8, lane, acc);
      }
      epi(sm, acc, (pp? c1+8 : c1), ph*2+1, pp*2+uu, ntq, wm, lane, ph!=0, h1w, 136);
    }
    // ---- tail ----
    if(!ph){
      if(tid<64){
        float xv[6];
        if(t+1<50){
          const float* hp = history + (((size_t)(b0+tid)*8)*50 + (size_t)(t+1))*6;
#pragma unroll
          for(int f=0;f<6;++f) xv[f]=hp[f];
        } else { xv[0]=st0; xv[1]=st1; xv[2]=0; xv[3]=0; xv[4]=0; xv[5]=0; }
#pragma unroll
        for(int f=0;f<6;++f){
          __half hh=__float2half_rn(xv[f]);
          *(u16*)(sm + h0w + (u32)(tid*152+128+f)*2u) = *(u16*)&hh;
        }
      }
      BARC();
    } else {
      BARC();
      if(tid<128){
        int ss=tid>>1, o=tid&1;
        float y = ((float*)(sm+PSUM))[tid] + outb[o];
        out[((size_t)(b0+ss)*60 + (size_t)(t-50))*2 + o] = y;
        ((float*)(sm+PSUM))[tid]=0.f;
        __half hh=__float2half_rn(y);
        *(u16*)(sm + h0w + (u32)(ss*152+128+o)*2u) = *(u16*)&hh;
      }
      BARC();
    }
  }
}

extern "C" void kernel_launch(void* const* d_in, const int* in_sizes, int n_in,
                              void* d_out, int out_size){
  const float* history     = (const float*)d_in[0];
  const float* start_token = (const float*)d_in[1];
  const float* eWih0=(const float*)d_in[2],  *eWhh0=(const float*)d_in[3],  *eb0=(const float*)d_in[4];
  const float* eWih1=(const float*)d_in[5],  *eWhh1=(const float*)d_in[6],  *eb1=(const float*)d_in[7];
  const float* dWih0=(const float*)d_in[8],  *dWhh0=(const float*)d_in[9],  *db0=(const float*)d_in[10];
  const float* dWih1=(const float*)d_in[11], *dWhh1=(const float*)d_in[12], *db1=(const float*)d_in[13];
  const float* outW=(const float*)d_in[14],  *outb=(const float*)d_in[15];
  float* out=(float*)d_out;
  (void)in_sizes; (void)n_in; (void)out_size;

  cudaFuncSetAttribute(lstm_hmma_kernel, cudaFuncAttributeMaxDynamicSharedMemorySize, SMSZ);

  prep_kernel<<<208, 256>>>(eWih0,eWhh0,eWih1,eWhh1,dWih0,dWhh0,dWih1,dWhh1);
  lstm_hmma_kernel<<<256, 544, SMSZ>>>(history,start_token,eb0,eb1,db0,db1,outW,outb,out);
}